// round 1
// baseline (speedup 1.0000x reference)
#include <cuda_runtime.h>

#define BB 2
#define TT 2048
#define DD 1024
#define HH 16
#define HD 64
#define M_ROWS (BB*TT)   // 4096

// Scratch (static device globals; allocation-free per harness rules)
__device__ float g_q[BB*HH*TT*HD];   // (b,h,t,d)
__device__ float g_k[BB*HH*TT*HD];
__device__ float g_v[BB*HH*TT*HD];
__device__ float g_ao[BB*TT*HH*HD];  // (b,t,h,d) rows for O-proj

// ---------------------------------------------------------------------------
// SGEMM: C = A[M,K] @ W[N,K]^T   (both row-major, K contiguous), M=4096, N=K=1024
// MODE 0: C[m*DD + n]
// MODE 1: scatter to (b,h,t,d):  m = b*TT+t, n = h*HD+d
// ---------------------------------------------------------------------------
template<int MODE>
__global__ __launch_bounds__(256)
void gemm_kernel(const float* __restrict__ A, const float* __restrict__ W,
                 float* __restrict__ C) {
    const int BM = 128, BN = 128, BK = 16;
    __shared__ float As[BK][BM];
    __shared__ float Ws[BK][BN];

    const int tid = threadIdx.x;
    const int m0 = blockIdx.y * BM;
    const int n0 = blockIdx.x * BN;
    const int tx = tid & 15;        // 0..15
    const int ty = tid >> 4;        // 0..15

    float acc[8][8];
    #pragma unroll
    for (int i = 0; i < 8; i++)
        #pragma unroll
        for (int j = 0; j < 8; j++) acc[i][j] = 0.f;

    const int lr = tid >> 2;        // 0..63
    const int lc = tid & 3;         // 0..3  (float4 column)

    for (int k0 = 0; k0 < DD; k0 += BK) {
        #pragma unroll
        for (int r = 0; r < 2; r++) {
            const int row = lr + r * 64;
            float4 va = *(const float4*)&A[(size_t)(m0 + row) * DD + k0 + lc * 4];
            As[lc*4+0][row] = va.x; As[lc*4+1][row] = va.y;
            As[lc*4+2][row] = va.z; As[lc*4+3][row] = va.w;
            float4 vw = *(const float4*)&W[(size_t)(n0 + row) * DD + k0 + lc * 4];
            Ws[lc*4+0][row] = vw.x; Ws[lc*4+1][row] = vw.y;
            Ws[lc*4+2][row] = vw.z; Ws[lc*4+3][row] = vw.w;
        }
        __syncthreads();

        #pragma unroll
        for (int k = 0; k < BK; k++) {
            float a[8], b[8];
            *(float4*)&a[0] = *(const float4*)&As[k][ty * 8];
            *(float4*)&a[4] = *(const float4*)&As[k][ty * 8 + 4];
            *(float4*)&b[0] = *(const float4*)&Ws[k][tx * 8];
            *(float4*)&b[4] = *(const float4*)&Ws[k][tx * 8 + 4];
            #pragma unroll
            for (int i = 0; i < 8; i++)
                #pragma unroll
                for (int j = 0; j < 8; j++)
                    acc[i][j] += a[i] * b[j];
        }
        __syncthreads();
    }

    #pragma unroll
    for (int i = 0; i < 8; i++) {
        const int m = m0 + ty * 8 + i;
        #pragma unroll
        for (int j = 0; j < 8; j++) {
            const int n = n0 + tx * 8 + j;
            if (MODE == 0) {
                C[(size_t)m * DD + n] = acc[i][j];
            } else {
                const int b = m / TT, t = m % TT;
                const int h = n / HD, d = n % HD;
                C[((size_t)(b * HH + h) * TT + t) * HD + d] = acc[i][j];
            }
        }
    }
}

// ---------------------------------------------------------------------------
// RoPE in-place on g_q and g_k, layout (b,h,t,d). freqs_cis: (T, 32, 2)=(cos,sin)
// ---------------------------------------------------------------------------
__global__ void rope_kernel(float* __restrict__ q, float* __restrict__ k,
                            const float* __restrict__ fc) {
    const int idx = blockIdx.x * blockDim.x + threadIdx.x;   // over (bh,t,i)
    const int total = BB * HH * TT * (HD / 2);
    if (idx >= total) return;
    const int i = idx & 31;
    const int t = (idx >> 5) & (TT - 1);
    const float c = fc[(t * 32 + i) * 2 + 0];
    const float s = fc[(t * 32 + i) * 2 + 1];
    const int base = idx * 2;   // == (bh*TT+t)*64 + 2*i
    float q0 = q[base], q1 = q[base + 1];
    q[base]     = q0 * c - q1 * s;
    q[base + 1] = q0 * s + q1 * c;
    float k0 = k[base], k1 = k[base + 1];
    k[base]     = k0 * c - k1 * s;
    k[base + 1] = k0 * s + k1 * c;
}

// ---------------------------------------------------------------------------
// Flash attention (fp32, causal). Thread-per-query, 32-key tiles in SMEM.
// q,k,v in (b,h,t,d); output scattered to (b,t,h,d).
// ---------------------------------------------------------------------------
__global__ __launch_bounds__(128)
void attn_kernel(const float* __restrict__ q, const float* __restrict__ k,
                 const float* __restrict__ v, float* __restrict__ out) {
    const int bh = blockIdx.y;
    const int tq = blockIdx.x * 128 + threadIdx.x;
    const float scale = 0.125f;   // 64^-0.5

    __shared__ float Ks[32][64];
    __shared__ float Vs[32][64];

    float qr[64];
    {
        const float* qp = q + ((size_t)bh * TT + tq) * HD;
        #pragma unroll
        for (int d4 = 0; d4 < 16; d4++) {
            float4 t4 = *(const float4*)&qp[d4 * 4];
            qr[d4*4+0] = t4.x * scale; qr[d4*4+1] = t4.y * scale;
            qr[d4*4+2] = t4.z * scale; qr[d4*4+3] = t4.w * scale;
        }
    }

    float o[64];
    #pragma unroll
    for (int d = 0; d < 64; d++) o[d] = 0.f;
    float mi = -1e30f, li = 0.f;

    const int ntiles = (blockIdx.x + 1) * 4;   // keys up to block's max query
    const float* kbase = k + (size_t)bh * TT * HD;
    const float* vbase = v + (size_t)bh * TT * HD;

    for (int tile = 0; tile < ntiles; tile++) {
        const int tk0 = tile * 32;
        __syncthreads();
        {
            const float4* ksrc = (const float4*)(kbase + (size_t)tk0 * HD);
            const float4* vsrc = (const float4*)(vbase + (size_t)tk0 * HD);
            #pragma unroll
            for (int r = 0; r < 4; r++) {
                const int f4 = threadIdx.x + r * 128;   // 512 float4 per tile
                ((float4*)Ks)[f4] = ksrc[f4];
                ((float4*)Vs)[f4] = vsrc[f4];
            }
        }
        __syncthreads();

        float s[32];
        #pragma unroll
        for (int j = 0; j < 32; j++) {
            float acc = 0.f;
            #pragma unroll
            for (int d4 = 0; d4 < 16; d4++) {
                float4 kk = *(const float4*)&Ks[j][d4 * 4];
                acc += qr[d4*4+0]*kk.x + qr[d4*4+1]*kk.y
                     + qr[d4*4+2]*kk.z + qr[d4*4+3]*kk.w;
            }
            s[j] = acc;
        }

        float tmax = -1e30f;
        #pragma unroll
        for (int j = 0; j < 32; j++) {
            s[j] = (tk0 + j <= tq) ? s[j] : -1e30f;
            tmax = fmaxf(tmax, s[j]);
        }
        const float mnew = fmaxf(mi, tmax);
        const float corr = __expf(mi - mnew);
        float psum = 0.f;
        #pragma unroll
        for (int j = 0; j < 32; j++) {
            s[j] = __expf(s[j] - mnew);
            psum += s[j];
        }
        li = li * corr + psum;
        mi = mnew;
        #pragma unroll
        for (int d = 0; d < 64; d++) o[d] *= corr;

        #pragma unroll
        for (int j = 0; j < 32; j++) {
            const float p = s[j];
            #pragma unroll
            for (int d4 = 0; d4 < 16; d4++) {
                float4 vv = *(const float4*)&Vs[j][d4 * 4];
                o[d4*4+0] += p * vv.x; o[d4*4+1] += p * vv.y;
                o[d4*4+2] += p * vv.z; o[d4*4+3] += p * vv.w;
            }
        }
    }

    const float inv = 1.f / li;
    const int b = bh / HH, h = bh % HH;
    float* op = out + (((size_t)b * TT + tq) * HH + h) * HD;
    #pragma unroll
    for (int d4 = 0; d4 < 16; d4++) {
        float4 t4;
        t4.x = o[d4*4+0] * inv; t4.y = o[d4*4+1] * inv;
        t4.z = o[d4*4+2] * inv; t4.w = o[d4*4+3] * inv;
        *(float4*)&op[d4 * 4] = t4;
    }
}

// ---------------------------------------------------------------------------
extern "C" void kernel_launch(void* const* d_in, const int* in_sizes, int n_in,
                              void* d_out, int out_size) {
    const float* x  = (const float*)d_in[0];
    const float* wq = (const float*)d_in[1];
    const float* wk = (const float*)d_in[2];
    const float* wv = (const float*)d_in[3];
    const float* wo = (const float*)d_in[4];
    const float* fc = (const float*)d_in[5];
    // d_in[6] = causal_mask (unused; causality handled analytically)
    float* out = (float*)d_out;

    float *qp, *kp, *vp, *aop;
    cudaGetSymbolAddress((void**)&qp,  g_q);
    cudaGetSymbolAddress((void**)&kp,  g_k);
    cudaGetSymbolAddress((void**)&vp,  g_v);
    cudaGetSymbolAddress((void**)&aop, g_ao);

    dim3 ggrid(DD / 128, M_ROWS / 128);   // (8, 32)
    gemm_kernel<1><<<ggrid, 256>>>(x, wq, qp);
    gemm_kernel<1><<<ggrid, 256>>>(x, wk, kp);
    gemm_kernel<1><<<ggrid, 256>>>(x, wv, vp);

    const int pairs = BB * HH * TT * (HD / 2);
    rope_kernel<<<(pairs + 255) / 256, 256>>>(qp, kp, fc);

    dim3 agrid(TT / 128, BB * HH);        // (16, 32)
    attn_kernel<<<agrid, 128>>>(qp, kp, vp, aop);

    gemm_kernel<0><<<ggrid, 256>>>(aop, wo, out);
}

// round 3
// speedup vs baseline: 1.8193x; 1.8193x over previous
#include <cuda_runtime.h>
#include <cuda_bf16.h>
#include <cstdint>

#define BB 2
#define TT 2048
#define DD 1024
#define HH 16
#define HD 64
#define M_ROWS (BB*TT)   // 4096

typedef unsigned long long u64;

// Scratch (static device globals; allocation-free per harness rules)
__device__ float g_q[BB*HH*TT*HD];   // (b,h,t,d)
__device__ float g_k[BB*HH*TT*HD];
__device__ float g_v[BB*HH*TT*HD];
__device__ float g_ao[BB*TT*HH*HD];  // (b,t,h,d) rows for O-proj

// ---------------------------------------------------------------------------
// helpers
// ---------------------------------------------------------------------------
__device__ __forceinline__ uint32_t b2u(__nv_bfloat162 h) {
    return *reinterpret_cast<uint32_t*>(&h);
}

__device__ __forceinline__ void mma16816(float* c, const uint32_t* a, const uint32_t* b) {
    asm volatile(
        "mma.sync.aligned.m16n8k16.row.col.f32.bf16.bf16.f32 "
        "{%0,%1,%2,%3}, {%4,%5,%6,%7}, {%8,%9}, {%0,%1,%2,%3};"
        : "+f"(c[0]), "+f"(c[1]), "+f"(c[2]), "+f"(c[3])
        : "r"(a[0]), "r"(a[1]), "r"(a[2]), "r"(a[3]), "r"(b[0]), "r"(b[1]));
}

__device__ __forceinline__ u64 pk2(float lo, float hi) {
    u64 r; asm("mov.b64 %0, {%1,%2};" : "=l"(r) : "f"(lo), "f"(hi)); return r;
}
__device__ __forceinline__ void upk2(u64 v, float& lo, float& hi) {
    asm("mov.b64 {%0,%1}, %2;" : "=f"(lo), "=f"(hi) : "l"(v));
}
__device__ __forceinline__ u64 fma2(u64 a, u64 b, u64 c) {
    u64 d; asm("fma.rn.f32x2 %0, %1, %2, %3;" : "=l"(d) : "l"(a), "l"(b), "l"(c)); return d;
}
__device__ __forceinline__ u64 mul2(u64 a, u64 b) {
    u64 d; asm("mul.rn.f32x2 %0, %1, %2;" : "=l"(d) : "l"(a), "l"(b)); return d;
}

// ---------------------------------------------------------------------------
// Tensor-core GEMM: C = A[M,1024] @ W[1024,1024]^T, M=4096.
// bf16 hi/lo split (3 MMAs) -> ~fp32 accuracy, fp32 accumulate.
// MODE 0: C row-major [m][n]
// MODE 1: scatter to (b,h,t,d):  m = b*TT+t, n = h*HD+d
// Block 128x128, BK=32, 256 threads (8 warps = 2(m) x 4(n), warp tile 64x32).
// SMEM holds fragments in mma-native layout: one LDS.128 per A frag.
// ---------------------------------------------------------------------------
template<int MODE>
__global__ __launch_bounds__(256, 1)
void gemm_mma(const float* __restrict__ A, const float* __restrict__ W,
              float* __restrict__ C) {
    // [split(hi/lo)][k_t(2)][m_tile(8)][lane(32)][reg(4)]
    __shared__ __align__(16) uint32_t As[2*2*8*32*4];   // 16KB
    // [split][k_t][n_tile(16)][lane(32)][reg(2)]
    __shared__ __align__(16) uint32_t Bs[2*2*16*32*2];  // 16KB

    const int tid  = threadIdx.x;
    const int lane = tid & 31;
    const int warp = tid >> 5;
    const int wm   = warp & 1;    // 0..1 (64 rows each)
    const int wn   = warp >> 1;   // 0..3 (32 cols each)
    const int m0   = blockIdx.y * 128;
    const int n0   = blockIdx.x * 128;

    float acc[4][4][4];
    #pragma unroll
    for (int i = 0; i < 4; i++)
        #pragma unroll
        for (int j = 0; j < 4; j++)
            #pragma unroll
            for (int r = 0; r < 4; r++) acc[i][j][r] = 0.f;

    float4 pa[4], pw[4];
    // initial prefetch, k0 = 0
    #pragma unroll
    for (int it = 0; it < 4; it++) {
        const int id = it * 256 + tid;
        const int r = id >> 3, c = id & 7;
        pa[it] = *(const float4*)&A[(size_t)(m0 + r) * 1024 + c * 4];
        pw[it] = *(const float4*)&W[(size_t)(n0 + r) * 1024 + c * 4];
    }

    for (int kb = 0; kb < 32; kb++) {
        // convert fp32 -> bf16 hi/lo, store in fragment-native layout
        #pragma unroll
        for (int it = 0; it < 4; it++) {
            const int id = it * 256 + tid;
            const int r = id >> 3, c = id & 7;
            const int kl = c << 2;
            const int kt = kl >> 4;
            const int kk = kl & 15;

            float4 va = pa[it];
            __nv_bfloat162 ah0 = __floats2bfloat162_rn(va.x, va.y);
            __nv_bfloat162 ah1 = __floats2bfloat162_rn(va.z, va.w);
            __nv_bfloat162 al0 = __floats2bfloat162_rn(
                va.x - __bfloat162float(ah0.x), va.y - __bfloat162float(ah0.y));
            __nv_bfloat162 al1 = __floats2bfloat162_rn(
                va.z - __bfloat162float(ah1.x), va.w - __bfloat162float(ah1.y));
            const int areg  = ((r >> 3) & 1) | ((kk >> 3) << 1);
            const int alane = ((r & 7) << 2) | ((kk >> 1) & 3);
            const int abase = ((kt << 3) | (r >> 4)) * 128 + (alane << 2) + areg;
            As[abase]        = b2u(ah0);
            As[abase + 4]    = b2u(ah1);
            As[2048 + abase]     = b2u(al0);
            As[2048 + abase + 4] = b2u(al1);

            float4 vw = pw[it];
            __nv_bfloat162 wh0 = __floats2bfloat162_rn(vw.x, vw.y);
            __nv_bfloat162 wh1 = __floats2bfloat162_rn(vw.z, vw.w);
            __nv_bfloat162 wl0 = __floats2bfloat162_rn(
                vw.x - __bfloat162float(wh0.x), vw.y - __bfloat162float(wh0.y));
            __nv_bfloat162 wl1 = __floats2bfloat162_rn(
                vw.z - __bfloat162float(wh1.x), vw.w - __bfloat162float(wh1.y));
            const int breg  = kk >> 3;
            const int blane = ((r & 7) << 2) | ((kk & 7) >> 1);
            const int bbase = ((kt << 4) | (r >> 3)) * 64 + (blane << 1) + breg;
            Bs[bbase]        = b2u(wh0);
            Bs[bbase + 2]    = b2u(wh1);
            Bs[2048 + bbase]     = b2u(wl0);
            Bs[2048 + bbase + 2] = b2u(wl1);
        }
        __syncthreads();

        if (kb < 31) {
            const int k0 = (kb + 1) * 32;
            #pragma unroll
            for (int it = 0; it < 4; it++) {
                const int id = it * 256 + tid;
                const int r = id >> 3, c = id & 7;
                pa[it] = *(const float4*)&A[(size_t)(m0 + r) * 1024 + k0 + c * 4];
                pw[it] = *(const float4*)&W[(size_t)(n0 + r) * 1024 + k0 + c * 4];
            }
        }

        #pragma unroll
        for (int kt2 = 0; kt2 < 2; kt2++) {
            uint4 Ah[4], Al[4];
            uint2 Bh[4], Bl[4];
            const uint32_t* pa_ = &As[(kt2 * 8 + wm * 4) * 128 + lane * 4];
            #pragma unroll
            for (int i = 0; i < 4; i++) {
                Ah[i] = *(const uint4*)(pa_ + i * 128);
                Al[i] = *(const uint4*)(pa_ + 2048 + i * 128);
            }
            const uint32_t* pb_ = &Bs[(kt2 * 16 + wn * 4) * 64 + lane * 2];
            #pragma unroll
            for (int i = 0; i < 4; i++) {
                Bh[i] = *(const uint2*)(pb_ + i * 64);
                Bl[i] = *(const uint2*)(pb_ + 2048 + i * 64);
            }
            #pragma unroll
            for (int mt = 0; mt < 4; mt++)
                #pragma unroll
                for (int nt = 0; nt < 4; nt++) {
                    mma16816(acc[mt][nt], (const uint32_t*)&Ah[mt], (const uint32_t*)&Bh[nt]);
                    mma16816(acc[mt][nt], (const uint32_t*)&Ah[mt], (const uint32_t*)&Bl[nt]);
                    mma16816(acc[mt][nt], (const uint32_t*)&Al[mt], (const uint32_t*)&Bh[nt]);
                }
        }
        __syncthreads();
    }

    // epilogue
    #pragma unroll
    for (int mt = 0; mt < 4; mt++) {
        #pragma unroll
        for (int nt = 0; nt < 4; nt++) {
            const int m = m0 + wm * 64 + mt * 16 + (lane >> 2);
            const int n = n0 + wn * 32 + nt * 8 + ((lane & 3) << 1);
            const float* c = acc[mt][nt];
            if (MODE == 0) {
                *(float2*)&C[(size_t)m * 1024 + n]       = make_float2(c[0], c[1]);
                *(float2*)&C[(size_t)(m + 8) * 1024 + n] = make_float2(c[2], c[3]);
            } else {
                const int b = m >> 11, t = m & 2047;
                const int h = n >> 6,  d = n & 63;
                const size_t base = ((size_t)(b * HH + h) * TT);
                *(float2*)&C[(base + t) * HD + d]     = make_float2(c[0], c[1]);
                *(float2*)&C[(base + t + 8) * HD + d] = make_float2(c[2], c[3]);
            }
        }
    }
}

// ---------------------------------------------------------------------------
// RoPE in-place on g_q and g_k, layout (b,h,t,d). freqs_cis: (T, 32, 2)=(cos,sin)
// ---------------------------------------------------------------------------
__global__ void rope_kernel(float* __restrict__ q, float* __restrict__ k,
                            const float* __restrict__ fc) {
    const int idx = blockIdx.x * blockDim.x + threadIdx.x;
    const int total = BB * HH * TT * (HD / 2);
    if (idx >= total) return;
    const int i = idx & 31;
    const int t = (idx >> 5) & (TT - 1);
    const float c = fc[(t * 32 + i) * 2 + 0];
    const float s = fc[(t * 32 + i) * 2 + 1];
    const int base = idx * 2;
    float q0 = q[base], q1 = q[base + 1];
    q[base]     = q0 * c - q1 * s;
    q[base + 1] = q0 * s + q1 * c;
    float k0 = k[base], k1 = k[base + 1];
    k[base]     = k0 * c - k1 * s;
    k[base + 1] = k0 * s + k1 * c;
}

// ---------------------------------------------------------------------------
// Flash attention (fp32, causal), packed f32x2 FMA. Thread-per-query.
// q,k,v in (b,h,t,d); output scattered to (b,t,h,d).
// ---------------------------------------------------------------------------
__global__ __launch_bounds__(128)
void attn_kernel(const float* __restrict__ q, const float* __restrict__ k,
                 const float* __restrict__ v, float* __restrict__ out) {
    const int bh = blockIdx.y;
    const int tq = blockIdx.x * 128 + threadIdx.x;
    const float scale = 0.125f;   // 64^-0.5

    __shared__ __align__(16) float Ks[32][64];
    __shared__ __align__(16) float Vs[32][64];

    u64 qp[32];
    {
        const float4* qptr = (const float4*)(q + ((size_t)bh * TT + tq) * HD);
        #pragma unroll
        for (int i = 0; i < 16; i++) {
            float4 t4 = qptr[i];
            qp[2*i]   = pk2(t4.x * scale, t4.y * scale);
            qp[2*i+1] = pk2(t4.z * scale, t4.w * scale);
        }
    }

    u64 o2[32];
    #pragma unroll
    for (int i = 0; i < 32; i++) o2[i] = 0ull;
    float mi = -1e30f, li = 0.f;

    const int ntiles = (blockIdx.x + 1) * 4;
    const float* kbase = k + (size_t)bh * TT * HD;
    const float* vbase = v + (size_t)bh * TT * HD;

    for (int tile = 0; tile < ntiles; tile++) {
        const int tk0 = tile * 32;
        __syncthreads();
        {
            const float4* ksrc = (const float4*)(kbase + (size_t)tk0 * HD);
            const float4* vsrc = (const float4*)(vbase + (size_t)tk0 * HD);
            #pragma unroll
            for (int r = 0; r < 4; r++) {
                const int f4 = threadIdx.x + r * 128;
                ((float4*)Ks)[f4] = ksrc[f4];
                ((float4*)Vs)[f4] = vsrc[f4];
            }
        }
        __syncthreads();

        float s[32];
        #pragma unroll
        for (int j = 0; j < 32; j++) {
            const ulonglong2* kp = (const ulonglong2*)Ks[j];
            u64 a0 = 0ull, a1 = 0ull;
            #pragma unroll
            for (int p2 = 0; p2 < 16; p2++) {   // 16 x 4 floats = full 64-dim row
                ulonglong2 kk = kp[p2];
                a0 = fma2(qp[2*p2],   kk.x, a0);
                a1 = fma2(qp[2*p2+1], kk.y, a1);
            }
            float x0, y0, x1, y1;
            upk2(a0, x0, y0);
            upk2(a1, x1, y1);
            s[j] = (x0 + y0) + (x1 + y1);
        }

        float tmax = -1e30f;
        #pragma unroll
        for (int j = 0; j < 32; j++) {
            s[j] = (tk0 + j <= tq) ? s[j] : -1e30f;
            tmax = fmaxf(tmax, s[j]);
        }
        const float mnew = fmaxf(mi, tmax);
        const float corr = __expf(mi - mnew);
        float psum = 0.f;
        #pragma unroll
        for (int j = 0; j < 32; j++) {
            s[j] = __expf(s[j] - mnew);
            psum += s[j];
        }
        li = li * corr + psum;
        mi = mnew;

        const u64 corr2 = pk2(corr, corr);
        #pragma unroll
        for (int i = 0; i < 32; i++) o2[i] = mul2(o2[i], corr2);

        #pragma unroll
        for (int j = 0; j < 32; j++) {
            const u64 pb = pk2(s[j], s[j]);
            const ulonglong2* vp = (const ulonglong2*)Vs[j];
            #pragma unroll
            for (int p2 = 0; p2 < 16; p2++) {   // full 64-dim row
                ulonglong2 vv = vp[p2];
                o2[2*p2]   = fma2(pb, vv.x, o2[2*p2]);
                o2[2*p2+1] = fma2(pb, vv.y, o2[2*p2+1]);
            }
        }
    }

    const float inv = 1.f / li;
    const int b = bh / HH, h = bh % HH;
    float* op = out + (((size_t)b * TT + tq) * HH + h) * HD;
    #pragma unroll
    for (int p2 = 0; p2 < 16; p2++) {   // write all 64 outputs
        float a, bq, c, d;
        upk2(o2[2*p2], a, bq);
        upk2(o2[2*p2+1], c, d);
        float4 t4 = make_float4(a * inv, bq * inv, c * inv, d * inv);
        *(float4*)&op[p2 * 4] = t4;
    }
}

// ---------------------------------------------------------------------------
extern "C" void kernel_launch(void* const* d_in, const int* in_sizes, int n_in,
                              void* d_out, int out_size) {
    const float* x  = (const float*)d_in[0];
    const float* wq = (const float*)d_in[1];
    const float* wk = (const float*)d_in[2];
    const float* wv = (const float*)d_in[3];
    const float* wo = (const float*)d_in[4];
    const float* fc = (const float*)d_in[5];
    float* out = (float*)d_out;

    float *qp, *kp, *vp, *aop;
    cudaGetSymbolAddress((void**)&qp,  g_q);
    cudaGetSymbolAddress((void**)&kp,  g_k);
    cudaGetSymbolAddress((void**)&vp,  g_v);
    cudaGetSymbolAddress((void**)&aop, g_ao);

    dim3 ggrid(DD / 128, M_ROWS / 128);   // (8, 32)
    gemm_mma<1><<<ggrid, 256>>>(x, wq, qp);
    gemm_mma<1><<<ggrid, 256>>>(x, wk, kp);
    gemm_mma<1><<<ggrid, 256>>>(x, wv, vp);

    const int pairs = BB * HH * TT * (HD / 2);
    rope_kernel<<<(pairs + 255) / 256, 256>>>(qp, kp, fc);

    dim3 agrid(TT / 128, BB * HH);        // (16, 32)
    attn_kernel<<<agrid, 128>>>(qp, kp, vp, aop);

    gemm_mma<0><<<ggrid, 256>>>(aop, wo, out);
}

// round 4
// speedup vs baseline: 2.5787x; 1.4174x over previous
#include <cuda_runtime.h>
#include <cuda_bf16.h>
#include <cstdint>

#define BB 2
#define TT 2048
#define DD 1024
#define HH 16
#define HD 64
#define M_ROWS (BB*TT)   // 4096

// ---------------------------------------------------------------------------
// Device scratch (allocation-free)
// ---------------------------------------------------------------------------
__device__ float g_q[BB*HH*TT*HD];           // fp32 (b,h,t,d) pre-rope
__device__ float g_k[BB*HH*TT*HD];
__device__ uint32_t g_qh[BB*HH*TT*32];       // bf16x2 pairs, post-rope, scaled
__device__ uint32_t g_ql[BB*HH*TT*32];
__device__ uint32_t g_kh[BB*HH*TT*32];
__device__ uint32_t g_kl[BB*HH*TT*32];
__device__ uint32_t g_vth[BB*HH*HD*TT/2];    // V transposed (bh,d,t) bf16 pairs along t
__device__ uint32_t g_vtl[BB*HH*HD*TT/2];
__device__ uint32_t g_xh[M_ROWS*512];        // x hi/lo bf16 pairs
__device__ uint32_t g_xl[M_ROWS*512];
__device__ uint32_t g_wqh[DD*512], g_wql[DD*512];
__device__ uint32_t g_wkh[DD*512], g_wkl[DD*512];
__device__ uint32_t g_wvh[DD*512], g_wvl[DD*512];
__device__ uint32_t g_woh[DD*512], g_wol[DD*512];
__device__ uint32_t g_aoh[M_ROWS*512];       // attn out (b,t,h,d) hi/lo
__device__ uint32_t g_aol[M_ROWS*512];

// ---------------------------------------------------------------------------
// helpers
// ---------------------------------------------------------------------------
__device__ __forceinline__ void mma16816(float* c, const uint32_t* a, const uint32_t* b) {
    asm volatile(
        "mma.sync.aligned.m16n8k16.row.col.f32.bf16.bf16.f32 "
        "{%0,%1,%2,%3}, {%4,%5,%6,%7}, {%8,%9}, {%0,%1,%2,%3};"
        : "+f"(c[0]), "+f"(c[1]), "+f"(c[2]), "+f"(c[3])
        : "r"(a[0]), "r"(a[1]), "r"(a[2]), "r"(a[3]), "r"(b[0]), "r"(b[1]));
}

__device__ __forceinline__ uint32_t split_pair(float a, float b, uint32_t& lo) {
    __nv_bfloat162 h = __floats2bfloat162_rn(a, b);
    float ra = a - __bfloat162float(h.x);
    float rb = b - __bfloat162float(h.y);
    __nv_bfloat162 l = __floats2bfloat162_rn(ra, rb);
    lo = *reinterpret_cast<uint32_t*>(&l);
    return *reinterpret_cast<uint32_t*>(&h);
}

// ---------------------------------------------------------------------------
// split fp32 -> bf16 hi/lo pairs
// ---------------------------------------------------------------------------
__global__ void split_kernel(const float2* __restrict__ src,
                             uint32_t* __restrict__ dh, uint32_t* __restrict__ dl,
                             int npairs) {
    int i = blockIdx.x * blockDim.x + threadIdx.x;
    if (i >= npairs) return;
    float2 v = src[i];
    uint32_t lo;
    uint32_t hi = split_pair(v.x, v.y, lo);
    dh[i] = hi; dl[i] = lo;
}

// ---------------------------------------------------------------------------
// Tensor-core GEMM on pre-split bf16 hi/lo: C = A @ W^T (logical fp32).
// MODE 0: C fp32 row-major [m][1024]
// MODE 1: C fp32 scatter to (b,h,t,d)
// MODE 2: write bf16 hi/lo to V-transposed layout (bh,d,t)
// Block 128x128, BK=32, 256 threads, warp tile 64x32, 3-MMA hi/lo split.
// ---------------------------------------------------------------------------
template<int MODE>
__global__ __launch_bounds__(256)
void gemm_mma(const uint32_t* __restrict__ Ah, const uint32_t* __restrict__ Al,
              const uint32_t* __restrict__ Wh, const uint32_t* __restrict__ Wl,
              float* __restrict__ C,
              __nv_bfloat16* __restrict__ Cbh, __nv_bfloat16* __restrict__ Cbl) {
    __shared__ __align__(16) uint32_t As[2*2048];   // [split][kt2][mtile8][lane32][reg4]
    __shared__ __align__(16) uint32_t Bs[2*2048];   // [split][kt2][ntile16][lane32][reg2]

    const int tid  = threadIdx.x;
    const int lane = tid & 31;
    const int warp = tid >> 5;
    const int wm   = warp & 1;
    const int wn   = warp >> 1;
    const int m0   = blockIdx.y * 128;
    const int n0   = blockIdx.x * 128;

    float acc[4][4][4];
    #pragma unroll
    for (int i = 0; i < 4; i++)
        #pragma unroll
        for (int j = 0; j < 4; j++)
            #pragma unroll
            for (int r = 0; r < 4; r++) acc[i][j][r] = 0.f;

    uint4 rAh[2], rAl[2], rWh[2], rWl[2];
    #pragma unroll
    for (int half = 0; half < 2; half++) {
        const int id = half * 256 + tid;
        const int r = id >> 2, c8 = id & 3;
        rAh[half] = *(const uint4*)&Ah[(size_t)(m0 + r) * 512 + c8 * 4];
        rAl[half] = *(const uint4*)&Al[(size_t)(m0 + r) * 512 + c8 * 4];
        rWh[half] = *(const uint4*)&Wh[(size_t)(n0 + r) * 512 + c8 * 4];
        rWl[half] = *(const uint4*)&Wl[(size_t)(n0 + r) * 512 + c8 * 4];
    }

    for (int kb = 0; kb < 32; kb++) {
        #pragma unroll
        for (int half = 0; half < 2; half++) {
            const int id = half * 256 + tid;
            const int r = id >> 2, c8 = id & 3;
            const int kt = c8 >> 1, khalf = c8 & 1;
            const int areg = ((r >> 3) & 1) | (khalf << 1);
            const int ab = ((kt << 3) | (r >> 4)) * 128 + (r & 7) * 16 + areg;
            const uint32_t* ah = (const uint32_t*)&rAh[half];
            const uint32_t* al = (const uint32_t*)&rAl[half];
            #pragma unroll
            for (int j = 0; j < 4; j++) {
                As[ab + j * 4]        = ah[j];
                As[2048 + ab + j * 4] = al[j];
            }
            const int breg = khalf;
            const int bb = ((kt << 4) | (r >> 3)) * 64 + (r & 7) * 8 + breg;
            const uint32_t* wh = (const uint32_t*)&rWh[half];
            const uint32_t* wl = (const uint32_t*)&rWl[half];
            #pragma unroll
            for (int j = 0; j < 4; j++) {
                Bs[bb + j * 2]        = wh[j];
                Bs[2048 + bb + j * 2] = wl[j];
            }
        }
        __syncthreads();

        if (kb < 31) {
            const int k0 = (kb + 1) * 16;   // u32-pair units
            #pragma unroll
            for (int half = 0; half < 2; half++) {
                const int id = half * 256 + tid;
                const int r = id >> 2, c8 = id & 3;
                rAh[half] = *(const uint4*)&Ah[(size_t)(m0 + r) * 512 + k0 + c8 * 4];
                rAl[half] = *(const uint4*)&Al[(size_t)(m0 + r) * 512 + k0 + c8 * 4];
                rWh[half] = *(const uint4*)&Wh[(size_t)(n0 + r) * 512 + k0 + c8 * 4];
                rWl[half] = *(const uint4*)&Wl[(size_t)(n0 + r) * 512 + k0 + c8 * 4];
            }
        }

        #pragma unroll
        for (int kt2 = 0; kt2 < 2; kt2++) {
            uint4 Afh[4], Afl[4];
            uint2 Bfh[4], Bfl[4];
            const uint32_t* pa_ = &As[(kt2 * 8 + wm * 4) * 128 + lane * 4];
            #pragma unroll
            for (int i = 0; i < 4; i++) {
                Afh[i] = *(const uint4*)(pa_ + i * 128);
                Afl[i] = *(const uint4*)(pa_ + 2048 + i * 128);
            }
            const uint32_t* pb_ = &Bs[(kt2 * 16 + wn * 4) * 64 + lane * 2];
            #pragma unroll
            for (int i = 0; i < 4; i++) {
                Bfh[i] = *(const uint2*)(pb_ + i * 64);
                Bfl[i] = *(const uint2*)(pb_ + 2048 + i * 64);
            }
            #pragma unroll
            for (int mt = 0; mt < 4; mt++)
                #pragma unroll
                for (int nt = 0; nt < 4; nt++) {
                    mma16816(acc[mt][nt], (const uint32_t*)&Afh[mt], (const uint32_t*)&Bfh[nt]);
                    mma16816(acc[mt][nt], (const uint32_t*)&Afh[mt], (const uint32_t*)&Bfl[nt]);
                    mma16816(acc[mt][nt], (const uint32_t*)&Afl[mt], (const uint32_t*)&Bfh[nt]);
                }
        }
        __syncthreads();
    }

    // epilogue
    #pragma unroll
    for (int mt = 0; mt < 4; mt++) {
        #pragma unroll
        for (int nt = 0; nt < 4; nt++) {
            const int m = m0 + wm * 64 + mt * 16 + (lane >> 2);
            const int n = n0 + wn * 32 + nt * 8 + ((lane & 3) << 1);
            const float* c = acc[mt][nt];
            if (MODE == 0) {
                *(float2*)&C[(size_t)m * 1024 + n]       = make_float2(c[0], c[1]);
                *(float2*)&C[(size_t)(m + 8) * 1024 + n] = make_float2(c[2], c[3]);
            } else if (MODE == 1) {
                const int b = m >> 11, t = m & 2047;
                const int h = n >> 6,  d = n & 63;
                const size_t base = ((size_t)(b * HH + h) * TT);
                *(float2*)&C[(base + t) * HD + d]     = make_float2(c[0], c[1]);
                *(float2*)&C[(base + t + 8) * HD + d] = make_float2(c[2], c[3]);
            } else {
                // V transposed: (bh, d, t), bf16 hi/lo
                const int b = m >> 11, t = m & 2047;
                const int h = n >> 6,  d = n & 63;
                const size_t row0 = ((size_t)(b * HH + h) * HD + d) * TT;
                const size_t row1 = row0 + TT;   // d+1
                #pragma unroll
                for (int rr = 0; rr < 2; rr++) {
                    const int tt = t + rr * 8;
                    float v0 = c[rr * 2], v1 = c[rr * 2 + 1];
                    __nv_bfloat16 h0 = __float2bfloat16_rn(v0);
                    __nv_bfloat16 h1 = __float2bfloat16_rn(v1);
                    Cbh[row0 + tt] = h0;
                    Cbh[row1 + tt] = h1;
                    Cbl[row0 + tt] = __float2bfloat16_rn(v0 - __bfloat162float(h0));
                    Cbl[row1 + tt] = __float2bfloat16_rn(v1 - __bfloat162float(h1));
                }
            }
        }
    }
}

// ---------------------------------------------------------------------------
// RoPE: read fp32 q,k (b,h,t,d), rotate, write bf16 hi/lo pairs.
// Q is pre-scaled by 1/8 (softmax scale).
// ---------------------------------------------------------------------------
__global__ void rope2_kernel(const float* __restrict__ q, const float* __restrict__ k,
                             const float* __restrict__ fc,
                             uint32_t* __restrict__ qh, uint32_t* __restrict__ ql,
                             uint32_t* __restrict__ kh, uint32_t* __restrict__ kl) {
    const int idx = blockIdx.x * blockDim.x + threadIdx.x;
    const int total = BB * HH * TT * 32;
    if (idx >= total) return;
    const int i = idx & 31;
    const int t = (idx >> 5) & (TT - 1);
    const float c = fc[(t * 32 + i) * 2 + 0];
    const float s = fc[(t * 32 + i) * 2 + 1];
    const int base = idx * 2;

    float q0 = q[base], q1 = q[base + 1];
    float qr0 = (q0 * c - q1 * s) * 0.125f;
    float qr1 = (q0 * s + q1 * c) * 0.125f;
    uint32_t lo;
    qh[idx] = split_pair(qr0, qr1, lo);
    ql[idx] = lo;

    float k0 = k[base], k1 = k[base + 1];
    float kr0 = k0 * c - k1 * s;
    float kr1 = k0 * s + k1 * c;
    kh[idx] = split_pair(kr0, kr1, lo);
    kl[idx] = lo;
}

// ---------------------------------------------------------------------------
// Tensor-core flash attention (causal). 128 queries/block, 8 warps x 16 rows,
// 64-key tiles. 3-MMA hi/lo split for QK^T and PV. Output bf16 hi/lo (b,t,h,d).
// ---------------------------------------------------------------------------
__global__ __launch_bounds__(256)
void attn_mma(const uint32_t* __restrict__ qh, const uint32_t* __restrict__ ql,
              const uint32_t* __restrict__ kh, const uint32_t* __restrict__ kl,
              const uint32_t* __restrict__ vth, const uint32_t* __restrict__ vtl,
              uint32_t* __restrict__ aoh, uint32_t* __restrict__ aol) {
    const int bh = blockIdx.y;
    const int b  = bh >> 4, hhd = bh & 15;
    const int q0 = blockIdx.x * 128;
    const int tid = threadIdx.x;
    const int lane = tid & 31;
    const int w = tid >> 5;

    __shared__ __align__(16) uint32_t sm[8192];   // K frags [0,4096) , V frags [4096,8192)

    // ---- stage Q into fragment-native layout, then read to registers ----
    #pragma unroll
    for (int i = 0; i < 32; i++) {
        const int id = i * 256 + tid;
        const int s = id >> 12;
        const int row = (id >> 5) & 127;
        const int pr = id & 31;
        const uint32_t* src = s ? ql : qh;
        const uint32_t v = src[((size_t)bh * TT + q0 + row) * 32 + pr];
        const int wq_ = row >> 4, wrow = row & 15;
        const int ks = pr >> 3, kk2 = pr & 7;
        const int c = kk2 & 3, khalf = kk2 >> 2;
        const int areg = ((wrow >> 3) & 1) | (khalf << 1);
        sm[s * 4096 + ((wq_ * 4 + ks) * 32 + (wrow & 7) * 4 + c) * 4 + areg] = v;
    }
    __syncthreads();
    uint4 qfh[4], qfl[4];
    #pragma unroll
    for (int ks = 0; ks < 4; ks++) {
        qfh[ks] = *(const uint4*)&sm[((w * 4 + ks) * 32 + lane) * 4];
        qfl[ks] = *(const uint4*)&sm[4096 + ((w * 4 + ks) * 32 + lane) * 4];
    }

    float oacc[8][4];
    #pragma unroll
    for (int dt = 0; dt < 8; dt++)
        #pragma unroll
        for (int r = 0; r < 4; r++) oacc[dt][r] = 0.f;
    float mr0 = -1e30f, mr1 = -1e30f, lr0 = 0.f, lr1 = 0.f;

    const int r0 = q0 + w * 16;
    const int ntiles = blockIdx.x * 2 + 2;

    for (int kt = 0; kt < ntiles; kt++) {
        const int kt0 = kt * 64;
        __syncthreads();
        // load K tile -> B-frag layout (n=key, k=dim)
        #pragma unroll
        for (int i = 0; i < 16; i++) {
            const int id = i * 256 + tid;
            const int s = id >> 11;
            const int rem = id & 2047;
            const int key = rem >> 5, pr = rem & 31;
            const uint32_t* src = s ? kl : kh;
            const uint32_t v = src[((size_t)bh * TT + kt0 + key) * 32 + pr];
            const int ks = pr >> 3, kk2 = pr & 7;
            const int c = kk2 & 3, khalf = kk2 >> 2;
            sm[s * 2048 + ((ks * 8 + (key >> 3)) * 32 + (key & 7) * 4 + c) * 2 + khalf] = v;
        }
        // load V tile -> B-frag layout (n=dim, k=key)
        #pragma unroll
        for (int i = 0; i < 16; i++) {
            const int id = i * 256 + tid;
            const int s = id >> 11;
            const int rem = id & 2047;
            const int dim = rem >> 5, kp = rem & 31;
            const uint32_t* src = s ? vtl : vth;
            const uint32_t v = src[((size_t)bh * HD + dim) * (TT / 2) + (kt0 >> 1) + kp];
            const int ks = kp >> 3, kk2 = kp & 7;
            const int c = kk2 & 3, khalf = kk2 >> 2;
            sm[4096 + s * 2048 + ((ks * 8 + (dim >> 3)) * 32 + (dim & 7) * 4 + c) * 2 + khalf] = v;
        }
        __syncthreads();

        if (kt0 <= r0 + 15) {
            // ---- S = Q K^T ----
            float sacc[8][4];
            #pragma unroll
            for (int nt = 0; nt < 8; nt++) {
                #pragma unroll
                for (int r = 0; r < 4; r++) sacc[nt][r] = 0.f;
                #pragma unroll
                for (int ks = 0; ks < 4; ks++) {
                    uint2 kbh = *(const uint2*)&sm[((ks * 8 + nt) * 32 + lane) * 2];
                    uint2 kbl = *(const uint2*)&sm[2048 + ((ks * 8 + nt) * 32 + lane) * 2];
                    mma16816(sacc[nt], (const uint32_t*)&qfh[ks], (const uint32_t*)&kbh);
                    mma16816(sacc[nt], (const uint32_t*)&qfh[ks], (const uint32_t*)&kbl);
                    mma16816(sacc[nt], (const uint32_t*)&qfl[ks], (const uint32_t*)&kbh);
                }
            }
            // ---- causal mask (partial tiles only) ----
            if (kt0 + 63 > r0) {
                const int colb = kt0 + ((lane & 3) << 1);
                const int rowb = r0 + (lane >> 2);
                #pragma unroll
                for (int nt = 0; nt < 8; nt++) {
                    #pragma unroll
                    for (int r = 0; r < 4; r++) {
                        const int col = colb + nt * 8 + (r & 1);
                        const int row = rowb + ((r >> 1) << 3);
                        if (col > row) sacc[nt][r] = -1e30f;
                    }
                }
            }
            // ---- online softmax ----
            float mx0 = -1e30f, mx1 = -1e30f;
            #pragma unroll
            for (int nt = 0; nt < 8; nt++) {
                mx0 = fmaxf(mx0, fmaxf(sacc[nt][0], sacc[nt][1]));
                mx1 = fmaxf(mx1, fmaxf(sacc[nt][2], sacc[nt][3]));
            }
            mx0 = fmaxf(mx0, __shfl_xor_sync(0xffffffffu, mx0, 1));
            mx0 = fmaxf(mx0, __shfl_xor_sync(0xffffffffu, mx0, 2));
            mx1 = fmaxf(mx1, __shfl_xor_sync(0xffffffffu, mx1, 1));
            mx1 = fmaxf(mx1, __shfl_xor_sync(0xffffffffu, mx1, 2));
            const float mn0 = fmaxf(mr0, mx0);
            const float mn1 = fmaxf(mr1, mx1);
            const float corr0 = __expf(mr0 - mn0);
            const float corr1 = __expf(mr1 - mn1);
            mr0 = mn0; mr1 = mn1;
            float s0 = 0.f, s1 = 0.f;
            #pragma unroll
            for (int nt = 0; nt < 8; nt++) {
                sacc[nt][0] = __expf(sacc[nt][0] - mn0);
                sacc[nt][1] = __expf(sacc[nt][1] - mn0);
                sacc[nt][2] = __expf(sacc[nt][2] - mn1);
                sacc[nt][3] = __expf(sacc[nt][3] - mn1);
                s0 += sacc[nt][0] + sacc[nt][1];
                s1 += sacc[nt][2] + sacc[nt][3];
            }
            lr0 = lr0 * corr0 + s0;
            lr1 = lr1 * corr1 + s1;
            #pragma unroll
            for (int dt = 0; dt < 8; dt++) {
                oacc[dt][0] *= corr0; oacc[dt][1] *= corr0;
                oacc[dt][2] *= corr1; oacc[dt][3] *= corr1;
            }
            // ---- P fragments (acc -> A-frag, no shuffles) ----
            uint32_t pah[4][4], pal[4][4];
            #pragma unroll
            for (int ksp = 0; ksp < 4; ksp++) {
                pah[ksp][0] = split_pair(sacc[2*ksp][0],   sacc[2*ksp][1],   pal[ksp][0]);
                pah[ksp][1] = split_pair(sacc[2*ksp][2],   sacc[2*ksp][3],   pal[ksp][1]);
                pah[ksp][2] = split_pair(sacc[2*ksp+1][0], sacc[2*ksp+1][1], pal[ksp][2]);
                pah[ksp][3] = split_pair(sacc[2*ksp+1][2], sacc[2*ksp+1][3], pal[ksp][3]);
            }
            // ---- O += P V ----
            #pragma unroll
            for (int dt = 0; dt < 8; dt++) {
                #pragma unroll
                for (int ksp = 0; ksp < 4; ksp++) {
                    uint2 vbh = *(const uint2*)&sm[4096 + ((ksp * 8 + dt) * 32 + lane) * 2];
                    uint2 vbl = *(const uint2*)&sm[6144 + ((ksp * 8 + dt) * 32 + lane) * 2];
                    mma16816(oacc[dt], pah[ksp], (const uint32_t*)&vbh);
                    mma16816(oacc[dt], pal[ksp], (const uint32_t*)&vbh);
                    mma16816(oacc[dt], pah[ksp], (const uint32_t*)&vbl);
                }
            }
        }
    }

    // ---- epilogue ----
    lr0 += __shfl_xor_sync(0xffffffffu, lr0, 1);
    lr0 += __shfl_xor_sync(0xffffffffu, lr0, 2);
    lr1 += __shfl_xor_sync(0xffffffffu, lr1, 1);
    lr1 += __shfl_xor_sync(0xffffffffu, lr1, 2);
    const float inv0 = 1.f / lr0;
    const float inv1 = 1.f / lr1;
    const int t0 = r0 + (lane >> 2);
    const int t1 = t0 + 8;
    #pragma unroll
    for (int dt = 0; dt < 8; dt++) {
        uint32_t lo;
        uint32_t hi = split_pair(oacc[dt][0] * inv0, oacc[dt][1] * inv0, lo);
        const size_t i0 = (((size_t)b * TT + t0) * HH + hhd) * 32 + dt * 4 + (lane & 3);
        aoh[i0] = hi; aol[i0] = lo;
        hi = split_pair(oacc[dt][2] * inv1, oacc[dt][3] * inv1, lo);
        const size_t i1 = (((size_t)b * TT + t1) * HH + hhd) * 32 + dt * 4 + (lane & 3);
        aoh[i1] = hi; aol[i1] = lo;
    }
}

// ---------------------------------------------------------------------------
extern "C" void kernel_launch(void* const* d_in, const int* in_sizes, int n_in,
                              void* d_out, int out_size) {
    const float* x  = (const float*)d_in[0];
    const float* wq = (const float*)d_in[1];
    const float* wk = (const float*)d_in[2];
    const float* wv = (const float*)d_in[3];
    const float* wo = (const float*)d_in[4];
    const float* fc = (const float*)d_in[5];
    float* out = (float*)d_out;

    float *qp, *kp;
    uint32_t *qhp, *qlp, *khp, *klp, *vthp, *vtlp;
    uint32_t *xhp, *xlp, *aohp, *aolp;
    uint32_t *wqhp, *wqlp, *wkhp, *wklp, *wvhp, *wvlp, *wohp, *wolp;
    cudaGetSymbolAddress((void**)&qp,  g_q);
    cudaGetSymbolAddress((void**)&kp,  g_k);
    cudaGetSymbolAddress((void**)&qhp, g_qh);
    cudaGetSymbolAddress((void**)&qlp, g_ql);
    cudaGetSymbolAddress((void**)&khp, g_kh);
    cudaGetSymbolAddress((void**)&klp, g_kl);
    cudaGetSymbolAddress((void**)&vthp, g_vth);
    cudaGetSymbolAddress((void**)&vtlp, g_vtl);
    cudaGetSymbolAddress((void**)&xhp, g_xh);
    cudaGetSymbolAddress((void**)&xlp, g_xl);
    cudaGetSymbolAddress((void**)&aohp, g_aoh);
    cudaGetSymbolAddress((void**)&aolp, g_aol);
    cudaGetSymbolAddress((void**)&wqhp, g_wqh);
    cudaGetSymbolAddress((void**)&wqlp, g_wql);
    cudaGetSymbolAddress((void**)&wkhp, g_wkh);
    cudaGetSymbolAddress((void**)&wklp, g_wkl);
    cudaGetSymbolAddress((void**)&wvhp, g_wvh);
    cudaGetSymbolAddress((void**)&wvlp, g_wvl);
    cudaGetSymbolAddress((void**)&wohp, g_woh);
    cudaGetSymbolAddress((void**)&wolp, g_wol);

    // split inputs to bf16 hi/lo
    const int xpairs = M_ROWS * 512;
    const int wpairs = DD * 512;
    split_kernel<<<(xpairs + 255) / 256, 256>>>((const float2*)x, xhp, xlp, xpairs);
    split_kernel<<<(wpairs + 255) / 256, 256>>>((const float2*)wq, wqhp, wqlp, wpairs);
    split_kernel<<<(wpairs + 255) / 256, 256>>>((const float2*)wk, wkhp, wklp, wpairs);
    split_kernel<<<(wpairs + 255) / 256, 256>>>((const float2*)wv, wvhp, wvlp, wpairs);
    split_kernel<<<(wpairs + 255) / 256, 256>>>((const float2*)wo, wohp, wolp, wpairs);

    dim3 ggrid(DD / 128, M_ROWS / 128);   // (8, 32)
    gemm_mma<1><<<ggrid, 256>>>(xhp, xlp, wqhp, wqlp, qp, nullptr, nullptr);
    gemm_mma<1><<<ggrid, 256>>>(xhp, xlp, wkhp, wklp, kp, nullptr, nullptr);
    gemm_mma<2><<<ggrid, 256>>>(xhp, xlp, wvhp, wvlp, nullptr,
                                (__nv_bfloat16*)vthp, (__nv_bfloat16*)vtlp);

    const int rtot = BB * HH * TT * 32;
    rope2_kernel<<<(rtot + 255) / 256, 256>>>(qp, kp, fc, qhp, qlp, khp, klp);

    dim3 agrid(TT / 128, BB * HH);        // (16, 32)
    attn_mma<<<agrid, 256>>>(qhp, qlp, khp, klp, vthp, vtlp, aohp, aolp);

    gemm_mma<0><<<ggrid, 256>>>(aohp, aolp, wohp, wolp, out, nullptr, nullptr);
}

// round 6
// speedup vs baseline: 3.4971x; 1.3561x over previous
#include <cuda_runtime.h>
#include <cuda_bf16.h>
#include <cstdint>

#define BB 2
#define TT 2048
#define DD 1024
#define HH 16
#define HD 64
#define M_ROWS (BB*TT)   // 4096

// ---------------------------------------------------------------------------
// Device scratch (allocation-free). A-perm / B-perm = mma-fragment-image order.
// ---------------------------------------------------------------------------
__device__ float g_q[BB*HH*TT*HD];           // fp32 (b,h,t,d) pre-rope
__device__ float g_k[BB*HH*TT*HD];
__device__ uint32_t g_qh[BB*HH*TT*32];       // bf16x2 pairs, post-rope, scaled
__device__ uint32_t g_ql[BB*HH*TT*32];
__device__ uint32_t g_kh[BB*HH*TT*32];
__device__ uint32_t g_kl[BB*HH*TT*32];
__device__ uint32_t g_vth[BB*HH*HD*TT/2];    // V transposed (bh,d,t) bf16 pairs
__device__ uint32_t g_vtl[BB*HH*HD*TT/2];
__device__ uint32_t g_xh[M_ROWS*512];        // x, A-perm
__device__ uint32_t g_xl[M_ROWS*512];
__device__ uint32_t g_wqh[DD*512], g_wql[DD*512];   // weights, B-perm
__device__ uint32_t g_wkh[DD*512], g_wkl[DD*512];
__device__ uint32_t g_wvh[DD*512], g_wvl[DD*512];
__device__ uint32_t g_woh[DD*512], g_wol[DD*512];
__device__ uint32_t g_aoh[M_ROWS*512];       // attn out, A-perm
__device__ uint32_t g_aol[M_ROWS*512];

// ---------------------------------------------------------------------------
// helpers
// ---------------------------------------------------------------------------
__device__ __forceinline__ uint32_t smem_u32(const void* p) {
    return (uint32_t)__cvta_generic_to_shared(p);
}

#define CP16(d, s) asm volatile("cp.async.cg.shared.global [%0], [%1], 16;" \
                                :: "r"(d), "l"(s) : "memory")

__device__ __forceinline__ void mma16816(float* c, const uint32_t* a, const uint32_t* b) {
    asm volatile(
        "mma.sync.aligned.m16n8k16.row.col.f32.bf16.bf16.f32 "
        "{%0,%1,%2,%3}, {%4,%5,%6,%7}, {%8,%9}, {%0,%1,%2,%3};"
        : "+f"(c[0]), "+f"(c[1]), "+f"(c[2]), "+f"(c[3])
        : "r"(a[0]), "r"(a[1]), "r"(a[2]), "r"(a[3]), "r"(b[0]), "r"(b[1]));
}

__device__ __forceinline__ uint32_t split_pair(float a, float b, uint32_t& lo) {
    __nv_bfloat162 h = __floats2bfloat162_rn(a, b);
    float ra = a - __bfloat162float(h.x);
    float rb = b - __bfloat162float(h.y);
    __nv_bfloat162 l = __floats2bfloat162_rn(ra, rb);
    lo = *reinterpret_cast<uint32_t*>(&l);
    return *reinterpret_cast<uint32_t*>(&h);
}

// A-perm index: (m row 0..4095, kp pair 0..511) -> fragment-image slot
__device__ __forceinline__ size_t apermidx(int m, int kp) {
    const int mb = m >> 7, r = m & 127;
    const int kb = kp >> 4, kr = kp & 15;
    const int kt = kr >> 3, khalf = (kr >> 2) & 1, j = kr & 3;
    const int tile = kt * 8 + (r >> 4);
    const int lane = (r & 7) * 4 + j;
    const int areg = ((r >> 3) & 1) | (khalf << 1);
    return ((size_t)(mb * 32 + kb)) * 2048 + tile * 128 + lane * 4 + areg;
}
// B-perm index: (n row 0..1023/4095, kp pair) -> fragment-image slot
__device__ __forceinline__ size_t bpermidx(int n, int kp) {
    const int nb = n >> 7, r = n & 127;
    const int kb = kp >> 4, kr = kp & 15;
    const int kt = kr >> 3, khalf = (kr >> 2) & 1, j = kr & 3;
    return ((size_t)(nb * 32 + kb)) * 2048 +
           (kt * 16 + (r >> 3)) * 64 + ((r & 7) * 4 + j) * 2 + khalf;
}

// ---------------------------------------------------------------------------
// split fp32 -> bf16 hi/lo pairs, writing permuted fragment-image layouts
// ---------------------------------------------------------------------------
__global__ void split_permA(const float2* __restrict__ src,
                            uint32_t* __restrict__ dh, uint32_t* __restrict__ dl,
                            int total) {
    int i = blockIdx.x * blockDim.x + threadIdx.x;
    if (i >= total) return;
    float2 v = src[i];
    uint32_t lo, hi = split_pair(v.x, v.y, lo);
    const size_t idx = apermidx(i >> 9, i & 511);
    dh[idx] = hi; dl[idx] = lo;
}
__global__ void split_permB(const float2* __restrict__ src,
                            uint32_t* __restrict__ dh, uint32_t* __restrict__ dl,
                            int total) {
    int i = blockIdx.x * blockDim.x + threadIdx.x;
    if (i >= total) return;
    float2 v = src[i];
    uint32_t lo, hi = split_pair(v.x, v.y, lo);
    const size_t idx = bpermidx(i >> 9, i & 511);
    dh[idx] = hi; dl[idx] = lo;
}

// ---------------------------------------------------------------------------
// mma.sync GEMM with cp.async double-buffered mainloop on permuted operands.
// C = A @ W^T (logical fp32 via bf16 hi/lo, 3-MMA split). 128x128 tile, 8 warps.
// MODE 0: fp32 row-major; MODE 1: fp32 scatter (b,h,t,d); MODE 2: bf16 hi/lo V^T.
// ---------------------------------------------------------------------------
template<int MODE>
__global__ __launch_bounds__(256)
void gemm_cp(const uint32_t* __restrict__ Ah, const uint32_t* __restrict__ Al,
             const uint32_t* __restrict__ Wh, const uint32_t* __restrict__ Wl,
             float* __restrict__ C,
             __nv_bfloat16* __restrict__ Cbh, __nv_bfloat16* __restrict__ Cbl) {
    extern __shared__ __align__(16) uint32_t sm[];   // [2][4][2048] u32 = 64KB

    const int tid  = threadIdx.x;
    const int lane = tid & 31;
    const int w    = tid >> 5;
    const int wm   = w & 1;
    const int wn   = w >> 1;
    const int m0   = blockIdx.y * 128;
    const int n0   = blockIdx.x * 128;
    const size_t abase = ((size_t)blockIdx.y * 32) * 2048;
    const size_t bbase = ((size_t)blockIdx.x * 32) * 2048;
    const uint32_t smaddr = smem_u32(sm);

    float acc[4][4][4];
    #pragma unroll
    for (int i = 0; i < 4; i++)
        #pragma unroll
        for (int j = 0; j < 4; j++)
            #pragma unroll
            for (int r = 0; r < 4; r++) acc[i][j][r] = 0.f;

    // issue one stage: 4 buffers x 8KB, each thread 32B per buffer
    auto issue = [&](int st, int kb) {
        const uint32_t dbase = smaddr + (uint32_t)st * 32768u + tid * 32u;
        const size_t ko = (size_t)kb * 2048 + tid * 8;
        CP16(dbase,          Ah + abase + ko);
        CP16(dbase + 16,     Ah + abase + ko + 4);
        CP16(dbase + 8192,   Al + abase + ko);
        CP16(dbase + 8208,   Al + abase + ko + 4);
        CP16(dbase + 16384,  Wh + bbase + ko);
        CP16(dbase + 16400,  Wh + bbase + ko + 4);
        CP16(dbase + 24576,  Wl + bbase + ko);
        CP16(dbase + 24592,  Wl + bbase + ko + 4);
        asm volatile("cp.async.commit_group;" ::: "memory");
    };

    issue(0, 0);

    for (int kb = 0; kb < 32; kb++) {
        asm volatile("cp.async.wait_group 0;" ::: "memory");
        __syncthreads();
        if (kb < 31) issue((kb + 1) & 1, kb + 1);

        const uint32_t* As = sm + (kb & 1) * 8192;          // hi
        const uint32_t* Bs = As + 4096;                      // hi (lo at +2048 each)

        #pragma unroll
        for (int kt2 = 0; kt2 < 2; kt2++) {
            uint4 Afh[4], Afl[4];
            uint2 Bfh[4], Bfl[4];
            const uint32_t* pa_ = &As[(kt2 * 8 + wm * 4) * 128 + lane * 4];
            #pragma unroll
            for (int i = 0; i < 4; i++) {
                Afh[i] = *(const uint4*)(pa_ + i * 128);
                Afl[i] = *(const uint4*)(pa_ + 2048 + i * 128);
            }
            const uint32_t* pb_ = &Bs[(kt2 * 16 + wn * 4) * 64 + lane * 2];
            #pragma unroll
            for (int i = 0; i < 4; i++) {
                Bfh[i] = *(const uint2*)(pb_ + i * 64);
                Bfl[i] = *(const uint2*)(pb_ + 2048 + i * 64);
            }
            #pragma unroll
            for (int mt = 0; mt < 4; mt++)
                #pragma unroll
                for (int nt = 0; nt < 4; nt++) {
                    mma16816(acc[mt][nt], (const uint32_t*)&Afh[mt], (const uint32_t*)&Bfh[nt]);
                    mma16816(acc[mt][nt], (const uint32_t*)&Afh[mt], (const uint32_t*)&Bfl[nt]);
                    mma16816(acc[mt][nt], (const uint32_t*)&Afl[mt], (const uint32_t*)&Bfh[nt]);
                }
        }
    }

    // epilogue
    #pragma unroll
    for (int mt = 0; mt < 4; mt++) {
        #pragma unroll
        for (int nt = 0; nt < 4; nt++) {
            const int m = m0 + wm * 64 + mt * 16 + (lane >> 2);
            const int n = n0 + wn * 32 + nt * 8 + ((lane & 3) << 1);
            const float* c = acc[mt][nt];
            if (MODE == 0) {
                *(float2*)&C[(size_t)m * 1024 + n]       = make_float2(c[0], c[1]);
                *(float2*)&C[(size_t)(m + 8) * 1024 + n] = make_float2(c[2], c[3]);
            } else if (MODE == 1) {
                const int b = m >> 11, t = m & 2047;
                const int h = n >> 6,  d = n & 63;
                const size_t base = ((size_t)(b * HH + h) * TT);
                *(float2*)&C[(base + t) * HD + d]     = make_float2(c[0], c[1]);
                *(float2*)&C[(base + t + 8) * HD + d] = make_float2(c[2], c[3]);
            } else {
                const int b = m >> 11, t = m & 2047;
                const int h = n >> 6,  d = n & 63;
                const size_t row0 = ((size_t)(b * HH + h) * HD + d) * TT;
                const size_t row1 = row0 + TT;
                #pragma unroll
                for (int rr = 0; rr < 2; rr++) {
                    const int tt = t + rr * 8;
                    float v0 = c[rr * 2], v1 = c[rr * 2 + 1];
                    __nv_bfloat16 h0 = __float2bfloat16_rn(v0);
                    __nv_bfloat16 h1 = __float2bfloat16_rn(v1);
                    Cbh[row0 + tt] = h0;
                    Cbh[row1 + tt] = h1;
                    Cbl[row0 + tt] = __float2bfloat16_rn(v0 - __bfloat162float(h0));
                    Cbl[row1 + tt] = __float2bfloat16_rn(v1 - __bfloat162float(h1));
                }
            }
        }
    }
}

// ---------------------------------------------------------------------------
// RoPE: read fp32 q,k (b,h,t,d), rotate, write bf16 hi/lo pairs. Q pre-scaled.
// ---------------------------------------------------------------------------
__global__ void rope2_kernel(const float* __restrict__ q, const float* __restrict__ k,
                             const float* __restrict__ fc,
                             uint32_t* __restrict__ qh, uint32_t* __restrict__ ql,
                             uint32_t* __restrict__ kh, uint32_t* __restrict__ kl) {
    const int idx = blockIdx.x * blockDim.x + threadIdx.x;
    const int total = BB * HH * TT * 32;
    if (idx >= total) return;
    const int i = idx & 31;
    const int t = (idx >> 5) & (TT - 1);
    const float c = fc[(t * 32 + i) * 2 + 0];
    const float s = fc[(t * 32 + i) * 2 + 1];
    const int base = idx * 2;

    float q0 = q[base], q1 = q[base + 1];
    float qr0 = (q0 * c - q1 * s) * 0.125f;
    float qr1 = (q0 * s + q1 * c) * 0.125f;
    uint32_t lo;
    qh[idx] = split_pair(qr0, qr1, lo);
    ql[idx] = lo;

    float k0 = k[base], k1 = k[base + 1];
    float kr0 = k0 * c - k1 * s;
    float kr1 = k0 * s + k1 * c;
    kh[idx] = split_pair(kr0, kr1, lo);
    kl[idx] = lo;
}

// ---------------------------------------------------------------------------
// Tensor-core flash attention (mma.sync, causal). 128 q/block, 8 warps x 16 rows.
// Output written in A-perm layout for the O-projection GEMM.
// ---------------------------------------------------------------------------
__global__ __launch_bounds__(256)
void attn_mma(const uint32_t* __restrict__ qh, const uint32_t* __restrict__ ql,
              const uint32_t* __restrict__ kh, const uint32_t* __restrict__ kl,
              const uint32_t* __restrict__ vth, const uint32_t* __restrict__ vtl,
              uint32_t* __restrict__ aoh, uint32_t* __restrict__ aol) {
    const int bh = blockIdx.y;
    const int b  = bh >> 4, hhd = bh & 15;
    const int q0 = blockIdx.x * 128;
    const int tid = threadIdx.x;
    const int lane = tid & 31;
    const int w = tid >> 5;

    __shared__ __align__(16) uint32_t sm[8192];

    #pragma unroll
    for (int i = 0; i < 32; i++) {
        const int id = i * 256 + tid;
        const int s = id >> 12;
        const int row = (id >> 5) & 127;
        const int pr = id & 31;
        const uint32_t* src = s ? ql : qh;
        const uint32_t v = src[((size_t)bh * TT + q0 + row) * 32 + pr];
        const int wq_ = row >> 4, wrow = row & 15;
        const int ks = pr >> 3, kk2 = pr & 7;
        const int c = kk2 & 3, khalf = kk2 >> 2;
        const int areg = ((wrow >> 3) & 1) | (khalf << 1);
        sm[s * 4096 + ((wq_ * 4 + ks) * 32 + (wrow & 7) * 4 + c) * 4 + areg] = v;
    }
    __syncthreads();
    uint4 qfh[4], qfl[4];
    #pragma unroll
    for (int ks = 0; ks < 4; ks++) {
        qfh[ks] = *(const uint4*)&sm[((w * 4 + ks) * 32 + lane) * 4];
        qfl[ks] = *(const uint4*)&sm[4096 + ((w * 4 + ks) * 32 + lane) * 4];
    }

    float oacc[8][4];
    #pragma unroll
    for (int dt = 0; dt < 8; dt++)
        #pragma unroll
        for (int r = 0; r < 4; r++) oacc[dt][r] = 0.f;
    float mr0 = -1e30f, mr1 = -1e30f, lr0 = 0.f, lr1 = 0.f;

    const int r0 = q0 + w * 16;
    const int ntiles = blockIdx.x * 2 + 2;

    for (int kt = 0; kt < ntiles; kt++) {
        const int kt0 = kt * 64;
        __syncthreads();
        #pragma unroll
        for (int i = 0; i < 16; i++) {
            const int id = i * 256 + tid;
            const int s = id >> 11;
            const int rem = id & 2047;
            const int key = rem >> 5, pr = rem & 31;
            const uint32_t* src = s ? kl : kh;
            const uint32_t v = src[((size_t)bh * TT + kt0 + key) * 32 + pr];
            const int ks = pr >> 3, kk2 = pr & 7;
            const int c = kk2 & 3, khalf = kk2 >> 2;
            sm[s * 2048 + ((ks * 8 + (key >> 3)) * 32 + (key & 7) * 4 + c) * 2 + khalf] = v;
        }
        #pragma unroll
        for (int i = 0; i < 16; i++) {
            const int id = i * 256 + tid;
            const int s = id >> 11;
            const int rem = id & 2047;
            const int dim = rem >> 5, kp = rem & 31;
            const uint32_t* src = s ? vtl : vth;
            const uint32_t v = src[((size_t)bh * HD + dim) * (TT / 2) + (kt0 >> 1) + kp];
            const int ks = kp >> 3, kk2 = kp & 7;
            const int c = kk2 & 3, khalf = kk2 >> 2;
            sm[4096 + s * 2048 + ((ks * 8 + (dim >> 3)) * 32 + (dim & 7) * 4 + c) * 2 + khalf] = v;
        }
        __syncthreads();

        if (kt0 <= r0 + 15) {
            float sacc[8][4];
            #pragma unroll
            for (int nt = 0; nt < 8; nt++) {
                #pragma unroll
                for (int r = 0; r < 4; r++) sacc[nt][r] = 0.f;
                #pragma unroll
                for (int ks = 0; ks < 4; ks++) {
                    uint2 kbh = *(const uint2*)&sm[((ks * 8 + nt) * 32 + lane) * 2];
                    uint2 kbl = *(const uint2*)&sm[2048 + ((ks * 8 + nt) * 32 + lane) * 2];
                    mma16816(sacc[nt], (const uint32_t*)&qfh[ks], (const uint32_t*)&kbh);
                    mma16816(sacc[nt], (const uint32_t*)&qfh[ks], (const uint32_t*)&kbl);
                    mma16816(sacc[nt], (const uint32_t*)&qfl[ks], (const uint32_t*)&kbh);
                }
            }
            if (kt0 + 63 > r0) {
                const int colb = kt0 + ((lane & 3) << 1);
                const int rowb = r0 + (lane >> 2);
                #pragma unroll
                for (int nt = 0; nt < 8; nt++) {
                    #pragma unroll
                    for (int r = 0; r < 4; r++) {
                        const int col = colb + nt * 8 + (r & 1);
                        const int row = rowb + ((r >> 1) << 3);
                        if (col > row) sacc[nt][r] = -1e30f;
                    }
                }
            }
            float mx0 = -1e30f, mx1 = -1e30f;
            #pragma unroll
            for (int nt = 0; nt < 8; nt++) {
                mx0 = fmaxf(mx0, fmaxf(sacc[nt][0], sacc[nt][1]));
                mx1 = fmaxf(mx1, fmaxf(sacc[nt][2], sacc[nt][3]));
            }
            mx0 = fmaxf(mx0, __shfl_xor_sync(0xffffffffu, mx0, 1));
            mx0 = fmaxf(mx0, __shfl_xor_sync(0xffffffffu, mx0, 2));
            mx1 = fmaxf(mx1, __shfl_xor_sync(0xffffffffu, mx1, 1));
            mx1 = fmaxf(mx1, __shfl_xor_sync(0xffffffffu, mx1, 2));
            const float mn0 = fmaxf(mr0, mx0);
            const float mn1 = fmaxf(mr1, mx1);
            const float corr0 = __expf(mr0 - mn0);
            const float corr1 = __expf(mr1 - mn1);
            mr0 = mn0; mr1 = mn1;
            float s0 = 0.f, s1 = 0.f;
            #pragma unroll
            for (int nt = 0; nt < 8; nt++) {
                sacc[nt][0] = __expf(sacc[nt][0] - mn0);
                sacc[nt][1] = __expf(sacc[nt][1] - mn0);
                sacc[nt][2] = __expf(sacc[nt][2] - mn1);
                sacc[nt][3] = __expf(sacc[nt][3] - mn1);
                s0 += sacc[nt][0] + sacc[nt][1];
                s1 += sacc[nt][2] + sacc[nt][3];
            }
            lr0 = lr0 * corr0 + s0;
            lr1 = lr1 * corr1 + s1;
            #pragma unroll
            for (int dt = 0; dt < 8; dt++) {
                oacc[dt][0] *= corr0; oacc[dt][1] *= corr0;
                oacc[dt][2] *= corr1; oacc[dt][3] *= corr1;
            }
            uint32_t pah[4][4], pal[4][4];
            #pragma unroll
            for (int ksp = 0; ksp < 4; ksp++) {
                pah[ksp][0] = split_pair(sacc[2*ksp][0],   sacc[2*ksp][1],   pal[ksp][0]);
                pah[ksp][1] = split_pair(sacc[2*ksp][2],   sacc[2*ksp][3],   pal[ksp][1]);
                pah[ksp][2] = split_pair(sacc[2*ksp+1][0], sacc[2*ksp+1][1], pal[ksp][2]);
                pah[ksp][3] = split_pair(sacc[2*ksp+1][2], sacc[2*ksp+1][3], pal[ksp][3]);
            }
            #pragma unroll
            for (int dt = 0; dt < 8; dt++) {
                #pragma unroll
                for (int ksp = 0; ksp < 4; ksp++) {
                    uint2 vbh = *(const uint2*)&sm[4096 + ((ksp * 8 + dt) * 32 + lane) * 2];
                    uint2 vbl = *(const uint2*)&sm[6144 + ((ksp * 8 + dt) * 32 + lane) * 2];
                    mma16816(oacc[dt], pah[ksp], (const uint32_t*)&vbh);
                    mma16816(oacc[dt], pal[ksp], (const uint32_t*)&vbh);
                    mma16816(oacc[dt], pah[ksp], (const uint32_t*)&vbl);
                }
            }
        }
    }

    lr0 += __shfl_xor_sync(0xffffffffu, lr0, 1);
    lr0 += __shfl_xor_sync(0xffffffffu, lr0, 2);
    lr1 += __shfl_xor_sync(0xffffffffu, lr1, 1);
    lr1 += __shfl_xor_sync(0xffffffffu, lr1, 2);
    const float inv0 = 1.f / lr0;
    const float inv1 = 1.f / lr1;
    const int t0 = r0 + (lane >> 2);
    const int t1 = t0 + 8;
    #pragma unroll
    for (int dt = 0; dt < 8; dt++) {
        const int kp = hhd * 32 + dt * 4 + (lane & 3);
        uint32_t lo;
        uint32_t hi = split_pair(oacc[dt][0] * inv0, oacc[dt][1] * inv0, lo);
        const size_t i0 = apermidx(b * TT + t0, kp);
        aoh[i0] = hi; aol[i0] = lo;
        hi = split_pair(oacc[dt][2] * inv1, oacc[dt][3] * inv1, lo);
        const size_t i1 = apermidx(b * TT + t1, kp);
        aoh[i1] = hi; aol[i1] = lo;
    }
}

// ---------------------------------------------------------------------------
extern "C" void kernel_launch(void* const* d_in, const int* in_sizes, int n_in,
                              void* d_out, int out_size) {
    const float* x  = (const float*)d_in[0];
    const float* wq = (const float*)d_in[1];
    const float* wk = (const float*)d_in[2];
    const float* wv = (const float*)d_in[3];
    const float* wo = (const float*)d_in[4];
    const float* fc = (const float*)d_in[5];
    float* out = (float*)d_out;

    float *qp, *kp;
    uint32_t *qhp, *qlp, *khp, *klp, *vthp, *vtlp;
    uint32_t *xhp, *xlp, *aohp, *aolp;
    uint32_t *wqhp, *wqlp, *wkhp, *wklp, *wvhp, *wvlp, *wohp, *wolp;
    cudaGetSymbolAddress((void**)&qp,  g_q);
    cudaGetSymbolAddress((void**)&kp,  g_k);
    cudaGetSymbolAddress((void**)&qhp, g_qh);
    cudaGetSymbolAddress((void**)&qlp, g_ql);
    cudaGetSymbolAddress((void**)&khp, g_kh);
    cudaGetSymbolAddress((void**)&klp, g_kl);
    cudaGetSymbolAddress((void**)&vthp, g_vth);
    cudaGetSymbolAddress((void**)&vtlp, g_vtl);
    cudaGetSymbolAddress((void**)&xhp, g_xh);
    cudaGetSymbolAddress((void**)&xlp, g_xl);
    cudaGetSymbolAddress((void**)&aohp, g_aoh);
    cudaGetSymbolAddress((void**)&aolp, g_aol);
    cudaGetSymbolAddress((void**)&wqhp, g_wqh);
    cudaGetSymbolAddress((void**)&wqlp, g_wql);
    cudaGetSymbolAddress((void**)&wkhp, g_wkh);
    cudaGetSymbolAddress((void**)&wklp, g_wkl);
    cudaGetSymbolAddress((void**)&wvhp, g_wvh);
    cudaGetSymbolAddress((void**)&wvlp, g_wvl);
    cudaGetSymbolAddress((void**)&wohp, g_woh);
    cudaGetSymbolAddress((void**)&wolp, g_wol);

    const int DYNSZ = 65536;
    cudaFuncSetAttribute(gemm_cp<0>, cudaFuncAttributeMaxDynamicSharedMemorySize, DYNSZ);
    cudaFuncSetAttribute(gemm_cp<1>, cudaFuncAttributeMaxDynamicSharedMemorySize, DYNSZ);
    cudaFuncSetAttribute(gemm_cp<2>, cudaFuncAttributeMaxDynamicSharedMemorySize, DYNSZ);

    const int xpairs = M_ROWS * 512;
    const int wpairs = DD * 512;
    split_permA<<<(xpairs + 255) / 256, 256>>>((const float2*)x, xhp, xlp, xpairs);
    split_permB<<<(wpairs + 255) / 256, 256>>>((const float2*)wq, wqhp, wqlp, wpairs);
    split_permB<<<(wpairs + 255) / 256, 256>>>((const float2*)wk, wkhp, wklp, wpairs);
    split_permB<<<(wpairs + 255) / 256, 256>>>((const float2*)wv, wvhp, wvlp, wpairs);
    split_permB<<<(wpairs + 255) / 256, 256>>>((const float2*)wo, wohp, wolp, wpairs);

    dim3 ggrid(DD / 128, M_ROWS / 128);   // (8, 32)
    gemm_cp<1><<<ggrid, 256, DYNSZ>>>(xhp, xlp, wqhp, wqlp, qp, nullptr, nullptr);
    gemm_cp<1><<<ggrid, 256, DYNSZ>>>(xhp, xlp, wkhp, wklp, kp, nullptr, nullptr);
    gemm_cp<2><<<ggrid, 256, DYNSZ>>>(xhp, xlp, wvhp, wvlp, nullptr,
                                      (__nv_bfloat16*)vthp, (__nv_bfloat16*)vtlp);

    const int rtot = BB * HH * TT * 32;
    rope2_kernel<<<(rtot + 255) / 256, 256>>>(qp, kp, fc, qhp, qlp, khp, klp);

    dim3 agrid(TT / 128, BB * HH);        // (16, 32)
    attn_mma<<<agrid, 256>>>(qhp, qlp, khp, klp, vthp, vtlp, aohp, aolp);

    gemm_cp<0><<<ggrid, 256, DYNSZ>>>(aohp, aolp, wohp, wolp, out, nullptr, nullptr);
}

// round 7
// speedup vs baseline: 4.0042x; 1.1450x over previous
#include <cuda_runtime.h>
#include <cuda_bf16.h>
#include <cstdint>

#define BB 2
#define TT 2048
#define DD 1024
#define HH 16
#define HD 64
#define M_ROWS (BB*TT)   // 4096

// ---------------------------------------------------------------------------
// Device scratch (allocation-free). All tensor-op operands live in
// mma-fragment-image order in global memory.
// ---------------------------------------------------------------------------
__device__ float g_q[BB*HH*TT*HD];           // fp32 (b,h,t,d) pre-rope
__device__ float g_k[BB*HH*TT*HD];
__device__ uint32_t g_qfh[BB*HH*16*4096];    // Q A-frag image per 128-row block
__device__ uint32_t g_qfl[BB*HH*16*4096];
__device__ uint32_t g_kfh[BB*HH*32*2048];    // K B-frag image per 64-key tile
__device__ uint32_t g_kfl[BB*HH*32*2048];
__device__ uint32_t g_vfh[BB*HH*32*2048];    // V B-frag image per 64-key tile
__device__ uint32_t g_vfl[BB*HH*32*2048];
__device__ uint32_t g_xh[M_ROWS*512];        // x, A-perm
__device__ uint32_t g_xl[M_ROWS*512];
__device__ uint32_t g_wqh[DD*512], g_wql[DD*512];   // weights, B-perm
__device__ uint32_t g_wkh[DD*512], g_wkl[DD*512];
__device__ uint32_t g_wvh[DD*512], g_wvl[DD*512];
__device__ uint32_t g_woh[DD*512], g_wol[DD*512];
__device__ uint32_t g_aoh[M_ROWS*512];       // attn out, A-perm
__device__ uint32_t g_aol[M_ROWS*512];

// ---------------------------------------------------------------------------
// helpers
// ---------------------------------------------------------------------------
__device__ __forceinline__ uint32_t smem_u32(const void* p) {
    return (uint32_t)__cvta_generic_to_shared(p);
}

#define CP16(d, s) asm volatile("cp.async.cg.shared.global [%0], [%1], 16;" \
                                :: "r"(d), "l"(s) : "memory")

__device__ __forceinline__ void mma16816(float* c, const uint32_t* a, const uint32_t* b) {
    asm volatile(
        "mma.sync.aligned.m16n8k16.row.col.f32.bf16.bf16.f32 "
        "{%0,%1,%2,%3}, {%4,%5,%6,%7}, {%8,%9}, {%0,%1,%2,%3};"
        : "+f"(c[0]), "+f"(c[1]), "+f"(c[2]), "+f"(c[3])
        : "r"(a[0]), "r"(a[1]), "r"(a[2]), "r"(a[3]), "r"(b[0]), "r"(b[1]));
}

__device__ __forceinline__ uint32_t split_pair(float a, float b, uint32_t& lo) {
    __nv_bfloat162 h = __floats2bfloat162_rn(a, b);
    float ra = a - __bfloat162float(h.x);
    float rb = b - __bfloat162float(h.y);
    __nv_bfloat162 l = __floats2bfloat162_rn(ra, rb);
    lo = *reinterpret_cast<uint32_t*>(&l);
    return *reinterpret_cast<uint32_t*>(&h);
}

// A-perm index: (m row 0..4095, kp pair 0..511) -> fragment-image slot
__device__ __forceinline__ size_t apermidx(int m, int kp) {
    const int mb = m >> 7, r = m & 127;
    const int kb = kp >> 4, kr = kp & 15;
    const int kt = kr >> 3, khalf = (kr >> 2) & 1, j = kr & 3;
    const int tile = kt * 8 + (r >> 4);
    const int lane = (r & 7) * 4 + j;
    const int areg = ((r >> 3) & 1) | (khalf << 1);
    return ((size_t)(mb * 32 + kb)) * 2048 + tile * 128 + lane * 4 + areg;
}
// B-perm index: (n row, kp pair) -> fragment-image slot
__device__ __forceinline__ size_t bpermidx(int n, int kp) {
    const int nb = n >> 7, r = n & 127;
    const int kb = kp >> 4, kr = kp & 15;
    const int kt = kr >> 3, khalf = (kr >> 2) & 1, j = kr & 3;
    return ((size_t)(nb * 32 + kb)) * 2048 +
           (kt * 16 + (r >> 3)) * 64 + ((r & 7) * 4 + j) * 2 + khalf;
}

// ---------------------------------------------------------------------------
// split fp32 -> bf16 hi/lo pairs, writing permuted fragment-image layouts
// ---------------------------------------------------------------------------
__global__ void split_permA(const float2* __restrict__ src,
                            uint32_t* __restrict__ dh, uint32_t* __restrict__ dl,
                            int total) {
    int i = blockIdx.x * blockDim.x + threadIdx.x;
    if (i >= total) return;
    float2 v = src[i];
    uint32_t lo, hi = split_pair(v.x, v.y, lo);
    const size_t idx = apermidx(i >> 9, i & 511);
    dh[idx] = hi; dl[idx] = lo;
}
__global__ void split_permB(const float2* __restrict__ src,
                            uint32_t* __restrict__ dh, uint32_t* __restrict__ dl,
                            int total) {
    int i = blockIdx.x * blockDim.x + threadIdx.x;
    if (i >= total) return;
    float2 v = src[i];
    uint32_t lo, hi = split_pair(v.x, v.y, lo);
    const size_t idx = bpermidx(i >> 9, i & 511);
    dh[idx] = hi; dl[idx] = lo;
}

// ---------------------------------------------------------------------------
// mma.sync GEMM with cp.async double-buffered mainloop on permuted operands.
// MODE 0: fp32 row-major; MODE 1: fp32 scatter (b,h,t,d);
// MODE 2: write bf16 hi/lo scalar halves directly into V B-frag image.
// ---------------------------------------------------------------------------
template<int MODE>
__global__ __launch_bounds__(256)
void gemm_cp(const uint32_t* __restrict__ Ah, const uint32_t* __restrict__ Al,
             const uint32_t* __restrict__ Wh, const uint32_t* __restrict__ Wl,
             float* __restrict__ C,
             uint32_t* __restrict__ Cfh, uint32_t* __restrict__ Cfl) {
    extern __shared__ __align__(16) uint32_t sm[];   // 64KB

    const int tid  = threadIdx.x;
    const int lane = tid & 31;
    const int w    = tid >> 5;
    const int wm   = w & 1;
    const int wn   = w >> 1;
    const int m0   = blockIdx.y * 128;
    const int n0   = blockIdx.x * 128;
    const size_t abase = ((size_t)blockIdx.y * 32) * 2048;
    const size_t bbase = ((size_t)blockIdx.x * 32) * 2048;
    const uint32_t smaddr = smem_u32(sm);

    float acc[4][4][4];
    #pragma unroll
    for (int i = 0; i < 4; i++)
        #pragma unroll
        for (int j = 0; j < 4; j++)
            #pragma unroll
            for (int r = 0; r < 4; r++) acc[i][j][r] = 0.f;

    auto issue = [&](int st, int kb) {
        const uint32_t dbase = smaddr + (uint32_t)st * 32768u + tid * 32u;
        const size_t ko = (size_t)kb * 2048 + tid * 8;
        CP16(dbase,          Ah + abase + ko);
        CP16(dbase + 16,     Ah + abase + ko + 4);
        CP16(dbase + 8192,   Al + abase + ko);
        CP16(dbase + 8208,   Al + abase + ko + 4);
        CP16(dbase + 16384,  Wh + bbase + ko);
        CP16(dbase + 16400,  Wh + bbase + ko + 4);
        CP16(dbase + 24576,  Wl + bbase + ko);
        CP16(dbase + 24592,  Wl + bbase + ko + 4);
        asm volatile("cp.async.commit_group;" ::: "memory");
    };

    issue(0, 0);

    for (int kb = 0; kb < 32; kb++) {
        asm volatile("cp.async.wait_group 0;" ::: "memory");
        __syncthreads();
        if (kb < 31) issue((kb + 1) & 1, kb + 1);

        const uint32_t* As = sm + (kb & 1) * 8192;
        const uint32_t* Bs = As + 4096;

        #pragma unroll
        for (int kt2 = 0; kt2 < 2; kt2++) {
            uint4 Afh[4], Afl[4];
            uint2 Bfh[4], Bfl[4];
            const uint32_t* pa_ = &As[(kt2 * 8 + wm * 4) * 128 + lane * 4];
            #pragma unroll
            for (int i = 0; i < 4; i++) {
                Afh[i] = *(const uint4*)(pa_ + i * 128);
                Afl[i] = *(const uint4*)(pa_ + 2048 + i * 128);
            }
            const uint32_t* pb_ = &Bs[(kt2 * 16 + wn * 4) * 64 + lane * 2];
            #pragma unroll
            for (int i = 0; i < 4; i++) {
                Bfh[i] = *(const uint2*)(pb_ + i * 64);
                Bfl[i] = *(const uint2*)(pb_ + 2048 + i * 64);
            }
            #pragma unroll
            for (int mt = 0; mt < 4; mt++)
                #pragma unroll
                for (int nt = 0; nt < 4; nt++) {
                    mma16816(acc[mt][nt], (const uint32_t*)&Afh[mt], (const uint32_t*)&Bfh[nt]);
                    mma16816(acc[mt][nt], (const uint32_t*)&Afh[mt], (const uint32_t*)&Bfl[nt]);
                    mma16816(acc[mt][nt], (const uint32_t*)&Afl[mt], (const uint32_t*)&Bfh[nt]);
                }
        }
    }

    // epilogue
    #pragma unroll
    for (int mt = 0; mt < 4; mt++) {
        #pragma unroll
        for (int nt = 0; nt < 4; nt++) {
            const int m = m0 + wm * 64 + mt * 16 + (lane >> 2);
            const int n = n0 + wn * 32 + nt * 8 + ((lane & 3) << 1);
            const float* c = acc[mt][nt];
            if (MODE == 0) {
                *(float2*)&C[(size_t)m * 1024 + n]       = make_float2(c[0], c[1]);
                *(float2*)&C[(size_t)(m + 8) * 1024 + n] = make_float2(c[2], c[3]);
            } else if (MODE == 1) {
                const int b = m >> 11, t = m & 2047;
                const int h = n >> 6,  d = n & 63;
                const size_t base = ((size_t)(b * HH + h) * TT);
                *(float2*)&C[(base + t) * HD + d]     = make_float2(c[0], c[1]);
                *(float2*)&C[(base + t + 8) * HD + d] = make_float2(c[2], c[3]);
            } else {
                // V B-frag image: per (bh, 64-key tile), slot from (key-pair, dim),
                // 2-byte writes select the key half inside the packed bf16x2.
                const int b = m >> 11, t = m & 2047;
                const int h = n >> 6,  d = n & 63;
                const int bh2 = b * HH + h;
                #pragma unroll
                for (int rr = 0; rr < 2; rr++) {
                    const int tt = t + rr * 8;
                    const int kt3 = tt >> 6, kpp = (tt & 63) >> 1, hf = tt & 1;
                    const int ks3 = kpp >> 3, kk3 = kpp & 7;
                    const int c3 = kk3 & 3, kh3 = kk3 >> 2;
                    #pragma unroll
                    for (int jj = 0; jj < 2; jj++) {
                        const int dd = d + jj;
                        const int slot = ((ks3 * 8 + (dd >> 3)) * 32 + (dd & 7) * 4 + c3) * 2 + kh3;
                        const size_t u32i = (size_t)bh2 * 65536 + kt3 * 2048 + slot;
                        const float v = c[rr * 2 + jj];
                        __nv_bfloat16 hb = __float2bfloat16_rn(v);
                        __nv_bfloat16 lb = __float2bfloat16_rn(v - __bfloat162float(hb));
                        ((uint16_t*)Cfh)[u32i * 2 + hf] = *(uint16_t*)&hb;
                        ((uint16_t*)Cfl)[u32i * 2 + hf] = *(uint16_t*)&lb;
                    }
                }
            }
        }
    }
}

// ---------------------------------------------------------------------------
// RoPE: read fp32 q,k (b,h,t,d), rotate, write Q/K fragment images. Q pre-scaled.
// ---------------------------------------------------------------------------
__global__ void rope2_kernel(const float* __restrict__ q, const float* __restrict__ k,
                             const float* __restrict__ fc,
                             uint32_t* __restrict__ qfh, uint32_t* __restrict__ qfl,
                             uint32_t* __restrict__ kfh, uint32_t* __restrict__ kfl) {
    const int idx = blockIdx.x * blockDim.x + threadIdx.x;
    const int total = BB * HH * TT * 32;
    if (idx >= total) return;
    const int i = idx & 31;
    const int t = (idx >> 5) & (TT - 1);
    const int bh = idx >> 16;
    const float c = fc[(t * 32 + i) * 2 + 0];
    const float s = fc[(t * 32 + i) * 2 + 1];
    const int base = idx * 2;

    const int ks = i >> 3, kk2 = i & 7;
    const int c2 = kk2 & 3, khalf = kk2 >> 2;

    float q0 = q[base], q1 = q[base + 1];
    float qr0 = (q0 * c - q1 * s) * 0.125f;
    float qr1 = (q0 * s + q1 * c) * 0.125f;
    uint32_t lo;
    uint32_t hi = split_pair(qr0, qr1, lo);
    const int row = t & 127, qb = t >> 7;
    const int wq = row >> 4, wrow = row & 15;
    const int areg = ((wrow >> 3) & 1) | (khalf << 1);
    const size_t qdst = (size_t)bh * 65536 + qb * 4096 +
                        ((wq * 4 + ks) * 32 + (wrow & 7) * 4 + c2) * 4 + areg;
    qfh[qdst] = hi; qfl[qdst] = lo;

    float k0 = k[base], k1 = k[base + 1];
    float kr0 = k0 * c - k1 * s;
    float kr1 = k0 * s + k1 * c;
    hi = split_pair(kr0, kr1, lo);
    const int key = t & 63, ktile = t >> 6;
    const size_t kdst = (size_t)bh * 65536 + ktile * 2048 +
                        ((ks * 8 + (key >> 3)) * 32 + (key & 7) * 4 + c2) * 2 + khalf;
    kfh[kdst] = hi; kfl[kdst] = lo;
}

// ---------------------------------------------------------------------------
// Tensor-core flash attention (mma.sync, causal). 128 q/block, 8 warps x 16 rows.
// Q via direct LDG.128 (frag image); K/V via cp.async double-buffered ring.
// Output written in A-perm layout for the O-projection GEMM.
// ---------------------------------------------------------------------------
__global__ __launch_bounds__(256)
void attn_mma(const uint32_t* __restrict__ qfh, const uint32_t* __restrict__ qfl,
              const uint32_t* __restrict__ kfh, const uint32_t* __restrict__ kfl,
              const uint32_t* __restrict__ vfh, const uint32_t* __restrict__ vfl,
              uint32_t* __restrict__ aoh, uint32_t* __restrict__ aol) {
    extern __shared__ __align__(16) uint32_t sm[];   // 2 stages x 8192 u32 = 64KB
    const int bh = blockIdx.y;
    const int b  = bh >> 4, hhd = bh & 15;
    const int q0 = blockIdx.x * 128;
    const int tid = threadIdx.x;
    const int lane = tid & 31;
    const int w = tid >> 5;
    const uint32_t smaddr = smem_u32(sm);
    const size_t hbase = (size_t)bh * 65536;

    // Q fragments: direct vector loads, no staging
    uint4 qfh_r[4], qfl_r[4];
    {
        const size_t qb = hbase + (size_t)blockIdx.x * 4096;
        #pragma unroll
        for (int ks = 0; ks < 4; ks++) {
            const size_t o = qb + ((w * 4 + ks) * 32 + lane) * 4;
            qfh_r[ks] = *(const uint4*)&qfh[o];
            qfl_r[ks] = *(const uint4*)&qfl[o];
        }
    }

    float oacc[8][4];
    #pragma unroll
    for (int dt = 0; dt < 8; dt++)
        #pragma unroll
        for (int r = 0; r < 4; r++) oacc[dt][r] = 0.f;
    float mr0 = -1e30f, mr1 = -1e30f, lr0 = 0.f, lr1 = 0.f;

    const int r0 = q0 + w * 16;
    const int ntiles = blockIdx.x * 2 + 2;

    // stage layout (u32): [Kh 2048][Kl 2048][Vh 2048][Vl 2048]
    auto issue = [&](int st, int kt) {
        const uint32_t dbase = smaddr + (uint32_t)st * 32768u + tid * 32u;
        const size_t ko = hbase + (size_t)kt * 2048 + tid * 8;
        CP16(dbase,          kfh + ko);
        CP16(dbase + 16,     kfh + ko + 4);
        CP16(dbase + 8192,   kfl + ko);
        CP16(dbase + 8208,   kfl + ko + 4);
        CP16(dbase + 16384,  vfh + ko);
        CP16(dbase + 16400,  vfh + ko + 4);
        CP16(dbase + 24576,  vfl + ko);
        CP16(dbase + 24592,  vfl + ko + 4);
        asm volatile("cp.async.commit_group;" ::: "memory");
    };

    issue(0, 0);

    for (int kt = 0; kt < ntiles; kt++) {
        const int kt0 = kt * 64;
        asm volatile("cp.async.wait_group 0;" ::: "memory");
        __syncthreads();
        if (kt + 1 < ntiles) issue((kt + 1) & 1, kt + 1);

        const uint32_t* S = sm + (kt & 1) * 8192;

        if (kt0 <= r0 + 15) {
            float sacc[8][4];
            #pragma unroll
            for (int nt = 0; nt < 8; nt++) {
                #pragma unroll
                for (int r = 0; r < 4; r++) sacc[nt][r] = 0.f;
                #pragma unroll
                for (int ks = 0; ks < 4; ks++) {
                    uint2 kbh = *(const uint2*)&S[((ks * 8 + nt) * 32 + lane) * 2];
                    uint2 kbl = *(const uint2*)&S[2048 + ((ks * 8 + nt) * 32 + lane) * 2];
                    mma16816(sacc[nt], (const uint32_t*)&qfh_r[ks], (const uint32_t*)&kbh);
                    mma16816(sacc[nt], (const uint32_t*)&qfh_r[ks], (const uint32_t*)&kbl);
                    mma16816(sacc[nt], (const uint32_t*)&qfl_r[ks], (const uint32_t*)&kbh);
                }
            }
            if (kt0 + 63 > r0) {
                const int colb = kt0 + ((lane & 3) << 1);
                const int rowb = r0 + (lane >> 2);
                #pragma unroll
                for (int nt = 0; nt < 8; nt++) {
                    #pragma unroll
                    for (int r = 0; r < 4; r++) {
                        const int col = colb + nt * 8 + (r & 1);
                        const int row = rowb + ((r >> 1) << 3);
                        if (col > row) sacc[nt][r] = -1e30f;
                    }
                }
            }
            float mx0 = -1e30f, mx1 = -1e30f;
            #pragma unroll
            for (int nt = 0; nt < 8; nt++) {
                mx0 = fmaxf(mx0, fmaxf(sacc[nt][0], sacc[nt][1]));
                mx1 = fmaxf(mx1, fmaxf(sacc[nt][2], sacc[nt][3]));
            }
            mx0 = fmaxf(mx0, __shfl_xor_sync(0xffffffffu, mx0, 1));
            mx0 = fmaxf(mx0, __shfl_xor_sync(0xffffffffu, mx0, 2));
            mx1 = fmaxf(mx1, __shfl_xor_sync(0xffffffffu, mx1, 1));
            mx1 = fmaxf(mx1, __shfl_xor_sync(0xffffffffu, mx1, 2));
            const float mn0 = fmaxf(mr0, mx0);
            const float mn1 = fmaxf(mr1, mx1);
            const float corr0 = __expf(mr0 - mn0);
            const float corr1 = __expf(mr1 - mn1);
            mr0 = mn0; mr1 = mn1;
            float s0 = 0.f, s1 = 0.f;
            #pragma unroll
            for (int nt = 0; nt < 8; nt++) {
                sacc[nt][0] = __expf(sacc[nt][0] - mn0);
                sacc[nt][1] = __expf(sacc[nt][1] - mn0);
                sacc[nt][2] = __expf(sacc[nt][2] - mn1);
                sacc[nt][3] = __expf(sacc[nt][3] - mn1);
                s0 += sacc[nt][0] + sacc[nt][1];
                s1 += sacc[nt][2] + sacc[nt][3];
            }
            lr0 = lr0 * corr0 + s0;
            lr1 = lr1 * corr1 + s1;
            #pragma unroll
            for (int dt = 0; dt < 8; dt++) {
                oacc[dt][0] *= corr0; oacc[dt][1] *= corr0;
                oacc[dt][2] *= corr1; oacc[dt][3] *= corr1;
            }
            uint32_t pah[4][4], pal[4][4];
            #pragma unroll
            for (int ksp = 0; ksp < 4; ksp++) {
                pah[ksp][0] = split_pair(sacc[2*ksp][0],   sacc[2*ksp][1],   pal[ksp][0]);
                pah[ksp][1] = split_pair(sacc[2*ksp][2],   sacc[2*ksp][3],   pal[ksp][1]);
                pah[ksp][2] = split_pair(sacc[2*ksp+1][0], sacc[2*ksp+1][1], pal[ksp][2]);
                pah[ksp][3] = split_pair(sacc[2*ksp+1][2], sacc[2*ksp+1][3], pal[ksp][3]);
            }
            #pragma unroll
            for (int dt = 0; dt < 8; dt++) {
                #pragma unroll
                for (int ksp = 0; ksp < 4; ksp++) {
                    uint2 vbh = *(const uint2*)&S[4096 + ((ksp * 8 + dt) * 32 + lane) * 2];
                    uint2 vbl = *(const uint2*)&S[6144 + ((ksp * 8 + dt) * 32 + lane) * 2];
                    mma16816(oacc[dt], pah[ksp], (const uint32_t*)&vbh);
                    mma16816(oacc[dt], pal[ksp], (const uint32_t*)&vbh);
                    mma16816(oacc[dt], pah[ksp], (const uint32_t*)&vbl);
                }
            }
        }
    }

    lr0 += __shfl_xor_sync(0xffffffffu, lr0, 1);
    lr0 += __shfl_xor_sync(0xffffffffu, lr0, 2);
    lr1 += __shfl_xor_sync(0xffffffffu, lr1, 1);
    lr1 += __shfl_xor_sync(0xffffffffu, lr1, 2);
    const float inv0 = 1.f / lr0;
    const float inv1 = 1.f / lr1;
    const int t0 = r0 + (lane >> 2);
    const int t1 = t0 + 8;
    #pragma unroll
    for (int dt = 0; dt < 8; dt++) {
        const int kp = hhd * 32 + dt * 4 + (lane & 3);
        uint32_t lo;
        uint32_t hi = split_pair(oacc[dt][0] * inv0, oacc[dt][1] * inv0, lo);
        const size_t i0 = apermidx(b * TT + t0, kp);
        aoh[i0] = hi; aol[i0] = lo;
        hi = split_pair(oacc[dt][2] * inv1, oacc[dt][3] * inv1, lo);
        const size_t i1 = apermidx(b * TT + t1, kp);
        aoh[i1] = hi; aol[i1] = lo;
    }
}

// ---------------------------------------------------------------------------
extern "C" void kernel_launch(void* const* d_in, const int* in_sizes, int n_in,
                              void* d_out, int out_size) {
    const float* x  = (const float*)d_in[0];
    const float* wq = (const float*)d_in[1];
    const float* wk = (const float*)d_in[2];
    const float* wv = (const float*)d_in[3];
    const float* wo = (const float*)d_in[4];
    const float* fc = (const float*)d_in[5];
    float* out = (float*)d_out;

    float *qp, *kp;
    uint32_t *qfhp, *qflp, *kfhp, *kflp, *vfhp, *vflp;
    uint32_t *xhp, *xlp, *aohp, *aolp;
    uint32_t *wqhp, *wqlp, *wkhp, *wklp, *wvhp, *wvlp, *wohp, *wolp;
    cudaGetSymbolAddress((void**)&qp,  g_q);
    cudaGetSymbolAddress((void**)&kp,  g_k);
    cudaGetSymbolAddress((void**)&qfhp, g_qfh);
    cudaGetSymbolAddress((void**)&qflp, g_qfl);
    cudaGetSymbolAddress((void**)&kfhp, g_kfh);
    cudaGetSymbolAddress((void**)&kflp, g_kfl);
    cudaGetSymbolAddress((void**)&vfhp, g_vfh);
    cudaGetSymbolAddress((void**)&vflp, g_vfl);
    cudaGetSymbolAddress((void**)&xhp, g_xh);
    cudaGetSymbolAddress((void**)&xlp, g_xl);
    cudaGetSymbolAddress((void**)&aohp, g_aoh);
    cudaGetSymbolAddress((void**)&aolp, g_aol);
    cudaGetSymbolAddress((void**)&wqhp, g_wqh);
    cudaGetSymbolAddress((void**)&wqlp, g_wql);
    cudaGetSymbolAddress((void**)&wkhp, g_wkh);
    cudaGetSymbolAddress((void**)&wklp, g_wkl);
    cudaGetSymbolAddress((void**)&wvhp, g_wvh);
    cudaGetSymbolAddress((void**)&wvlp, g_wvl);
    cudaGetSymbolAddress((void**)&wohp, g_woh);
    cudaGetSymbolAddress((void**)&wolp, g_wol);

    const int DYNSZ = 65536;
    cudaFuncSetAttribute(gemm_cp<0>, cudaFuncAttributeMaxDynamicSharedMemorySize, DYNSZ);
    cudaFuncSetAttribute(gemm_cp<1>, cudaFuncAttributeMaxDynamicSharedMemorySize, DYNSZ);
    cudaFuncSetAttribute(gemm_cp<2>, cudaFuncAttributeMaxDynamicSharedMemorySize, DYNSZ);
    cudaFuncSetAttribute(attn_mma,   cudaFuncAttributeMaxDynamicSharedMemorySize, DYNSZ);

    const int xpairs = M_ROWS * 512;
    const int wpairs = DD * 512;
    split_permA<<<(xpairs + 255) / 256, 256>>>((const float2*)x, xhp, xlp, xpairs);
    split_permB<<<(wpairs + 255) / 256, 256>>>((const float2*)wq, wqhp, wqlp, wpairs);
    split_permB<<<(wpairs + 255) / 256, 256>>>((const float2*)wk, wkhp, wklp, wpairs);
    split_permB<<<(wpairs + 255) / 256, 256>>>((const float2*)wv, wvhp, wvlp, wpairs);
    split_permB<<<(wpairs + 255) / 256, 256>>>((const float2*)wo, wohp, wolp, wpairs);

    dim3 ggrid(DD / 128, M_ROWS / 128);   // (8, 32)
    gemm_cp<1><<<ggrid, 256, DYNSZ>>>(xhp, xlp, wqhp, wqlp, qp, nullptr, nullptr);
    gemm_cp<1><<<ggrid, 256, DYNSZ>>>(xhp, xlp, wkhp, wklp, kp, nullptr, nullptr);
    gemm_cp<2><<<ggrid, 256, DYNSZ>>>(xhp, xlp, wvhp, wvlp, nullptr, vfhp, vflp);

    const int rtot = BB * HH * TT * 32;
    rope2_kernel<<<(rtot + 255) / 256, 256>>>(qp, kp, fc, qfhp, qflp, kfhp, kflp);

    dim3 agrid(TT / 128, BB * HH);        // (16, 32)
    attn_mma<<<agrid, 256, DYNSZ>>>(qfhp, qflp, kfhp, kflp, vfhp, vflp, aohp, aolp);

    gemm_cp<0><<<ggrid, 256, DYNSZ>>>(aohp, aolp, wohp, wolp, out, nullptr, nullptr);
}

// round 8
// speedup vs baseline: 4.0661x; 1.0154x over previous
#include <cuda_runtime.h>
#include <cuda_bf16.h>
#include <cstdint>

#define BB 2
#define TT 2048
#define DD 1024
#define HH 16
#define HD 64
#define M_ROWS (BB*TT)   // 4096

// ---------------------------------------------------------------------------
// Device scratch (allocation-free). All tensor-op operands live in
// mma-fragment-image order in global memory.
// ---------------------------------------------------------------------------
__device__ uint32_t g_qfh[BB*HH*16*4096];    // Q A-frag image per 128-row block
__device__ uint32_t g_qfl[BB*HH*16*4096];
__device__ uint32_t g_kfh[BB*HH*32*2048];    // K B-frag image per 64-key tile
__device__ uint32_t g_kfl[BB*HH*32*2048];
__device__ uint32_t g_vfh[BB*HH*32*2048];    // V B-frag image per 64-key tile
__device__ uint32_t g_vfl[BB*HH*32*2048];
__device__ uint32_t g_xh[M_ROWS*512];        // x, A-perm
__device__ uint32_t g_xl[M_ROWS*512];
__device__ uint32_t g_wqh[DD*512], g_wql[DD*512];   // weights, B-perm
__device__ uint32_t g_wkh[DD*512], g_wkl[DD*512];
__device__ uint32_t g_wvh[DD*512], g_wvl[DD*512];
__device__ uint32_t g_woh[DD*512], g_wol[DD*512];
__device__ uint32_t g_aoh[M_ROWS*512];       // attn out, A-perm
__device__ uint32_t g_aol[M_ROWS*512];

// ---------------------------------------------------------------------------
// helpers
// ---------------------------------------------------------------------------
__device__ __forceinline__ uint32_t smem_u32(const void* p) {
    return (uint32_t)__cvta_generic_to_shared(p);
}

#define CP16(d, s) asm volatile("cp.async.cg.shared.global [%0], [%1], 16;" \
                                :: "r"(d), "l"(s) : "memory")

__device__ __forceinline__ void mma16816(float* c, const uint32_t* a, const uint32_t* b) {
    asm volatile(
        "mma.sync.aligned.m16n8k16.row.col.f32.bf16.bf16.f32 "
        "{%0,%1,%2,%3}, {%4,%5,%6,%7}, {%8,%9}, {%0,%1,%2,%3};"
        : "+f"(c[0]), "+f"(c[1]), "+f"(c[2]), "+f"(c[3])
        : "r"(a[0]), "r"(a[1]), "r"(a[2]), "r"(a[3]), "r"(b[0]), "r"(b[1]));
}

__device__ __forceinline__ uint32_t split_pair(float a, float b, uint32_t& lo) {
    __nv_bfloat162 h = __floats2bfloat162_rn(a, b);
    float ra = a - __bfloat162float(h.x);
    float rb = b - __bfloat162float(h.y);
    __nv_bfloat162 l = __floats2bfloat162_rn(ra, rb);
    lo = *reinterpret_cast<uint32_t*>(&l);
    return *reinterpret_cast<uint32_t*>(&h);
}

// A-perm index: (m row 0..4095, kp pair 0..511) -> fragment-image slot
__device__ __forceinline__ size_t apermidx(int m, int kp) {
    const int mb = m >> 7, r = m & 127;
    const int kb = kp >> 4, kr = kp & 15;
    const int kt = kr >> 3, khalf = (kr >> 2) & 1, j = kr & 3;
    const int tile = kt * 8 + (r >> 4);
    const int lane = (r & 7) * 4 + j;
    const int areg = ((r >> 3) & 1) | (khalf << 1);
    return ((size_t)(mb * 32 + kb)) * 2048 + tile * 128 + lane * 4 + areg;
}
// B-perm index: (n row, kp pair) -> fragment-image slot
__device__ __forceinline__ size_t bpermidx(int n, int kp) {
    const int nb = n >> 7, r = n & 127;
    const int kb = kp >> 4, kr = kp & 15;
    const int kt = kr >> 3, khalf = (kr >> 2) & 1, j = kr & 3;
    return ((size_t)(nb * 32 + kb)) * 2048 +
           (kt * 16 + (r >> 3)) * 64 + ((r & 7) * 4 + j) * 2 + khalf;
}
// Q-frag slot for (bh, t, pair i)
__device__ __forceinline__ size_t qfragidx(int bh, int t, int i) {
    const int ks = i >> 3, kk2 = i & 7;
    const int c2 = kk2 & 3, khalf = kk2 >> 2;
    const int row = t & 127, qb = t >> 7;
    const int wq = row >> 4, wrow = row & 15;
    const int areg = ((wrow >> 3) & 1) | (khalf << 1);
    return (size_t)bh * 65536 + qb * 4096 +
           ((wq * 4 + ks) * 32 + (wrow & 7) * 4 + c2) * 4 + areg;
}
// K-frag slot for (bh, t, pair i)
__device__ __forceinline__ size_t kfragidx(int bh, int t, int i) {
    const int ks = i >> 3, kk2 = i & 7;
    const int c2 = kk2 & 3, khalf = kk2 >> 2;
    const int key = t & 63, ktile = t >> 6;
    return (size_t)bh * 65536 + ktile * 2048 +
           ((ks * 8 + (key >> 3)) * 32 + (key & 7) * 4 + c2) * 2 + khalf;
}

// ---------------------------------------------------------------------------
// splits
// ---------------------------------------------------------------------------
__global__ void split_permA(const float2* __restrict__ src,
                            uint32_t* __restrict__ dh, uint32_t* __restrict__ dl,
                            int total) {
    int i = blockIdx.x * blockDim.x + threadIdx.x;
    if (i >= total) return;
    float2 v = src[i];
    uint32_t lo, hi = split_pair(v.x, v.y, lo);
    const size_t idx = apermidx(i >> 9, i & 511);
    dh[idx] = hi; dl[idx] = lo;
}
__global__ void split_permB4(const float2* __restrict__ s0, const float2* __restrict__ s1,
                             const float2* __restrict__ s2, const float2* __restrict__ s3,
                             uint32_t* __restrict__ h0, uint32_t* __restrict__ l0,
                             uint32_t* __restrict__ h1, uint32_t* __restrict__ l1,
                             uint32_t* __restrict__ h2, uint32_t* __restrict__ l2,
                             uint32_t* __restrict__ h3, uint32_t* __restrict__ l3,
                             int total) {
    int i = blockIdx.x * blockDim.x + threadIdx.x;
    if (i >= total) return;
    const int which = blockIdx.y;
    const float2* src = which == 0 ? s0 : which == 1 ? s1 : which == 2 ? s2 : s3;
    uint32_t* dh = which == 0 ? h0 : which == 1 ? h1 : which == 2 ? h2 : h3;
    uint32_t* dl = which == 0 ? l0 : which == 1 ? l1 : which == 2 ? l2 : l3;
    float2 v = src[i];
    uint32_t lo, hi = split_pair(v.x, v.y, lo);
    const size_t idx = bpermidx(i >> 9, i & 511);
    dh[idx] = hi; dl[idx] = lo;
}

// ---------------------------------------------------------------------------
// Fused QKV GEMM (grid.x = 24: 8 n-blocks x {Q,K,V}). cp.async mainloop.
// Epilogues: Q -> RoPE+scale -> Q frag image; K -> RoPE -> K frag image;
//            V -> V frag image (2-byte half writes).
// ---------------------------------------------------------------------------
__global__ __launch_bounds__(256)
void gemm_qkv(const uint32_t* __restrict__ Ah, const uint32_t* __restrict__ Al,
              const uint32_t* __restrict__ Wqh, const uint32_t* __restrict__ Wql,
              const uint32_t* __restrict__ Wkh, const uint32_t* __restrict__ Wkl,
              const uint32_t* __restrict__ Wvh, const uint32_t* __restrict__ Wvl,
              const float2* __restrict__ fc2,
              uint32_t* __restrict__ qfh, uint32_t* __restrict__ qfl,
              uint32_t* __restrict__ kfh, uint32_t* __restrict__ kfl,
              uint32_t* __restrict__ vfh, uint32_t* __restrict__ vfl) {
    extern __shared__ __align__(16) uint32_t sm[];   // 64KB

    const int which = blockIdx.x >> 3;               // 0=Q 1=K 2=V
    const int nblk  = blockIdx.x & 7;
    const uint32_t* Wh = which == 0 ? Wqh : which == 1 ? Wkh : Wvh;
    const uint32_t* Wl = which == 0 ? Wql : which == 1 ? Wkl : Wvl;

    const int tid  = threadIdx.x;
    const int lane = tid & 31;
    const int w    = tid >> 5;
    const int wm   = w & 1;
    const int wn   = w >> 1;
    const int m0   = blockIdx.y * 128;
    const int n0   = nblk * 128;
    const size_t abase = ((size_t)blockIdx.y * 32) * 2048;
    const size_t bbase = ((size_t)nblk * 32) * 2048;
    const uint32_t smaddr = smem_u32(sm);

    float acc[4][4][4];
    #pragma unroll
    for (int i = 0; i < 4; i++)
        #pragma unroll
        for (int j = 0; j < 4; j++)
            #pragma unroll
            for (int r = 0; r < 4; r++) acc[i][j][r] = 0.f;

    auto issue = [&](int st, int kb) {
        const uint32_t dbase = smaddr + (uint32_t)st * 32768u + tid * 32u;
        const size_t ko = (size_t)kb * 2048 + tid * 8;
        CP16(dbase,          Ah + abase + ko);
        CP16(dbase + 16,     Ah + abase + ko + 4);
        CP16(dbase + 8192,   Al + abase + ko);
        CP16(dbase + 8208,   Al + abase + ko + 4);
        CP16(dbase + 16384,  Wh + bbase + ko);
        CP16(dbase + 16400,  Wh + bbase + ko + 4);
        CP16(dbase + 24576,  Wl + bbase + ko);
        CP16(dbase + 24592,  Wl + bbase + ko + 4);
        asm volatile("cp.async.commit_group;" ::: "memory");
    };

    issue(0, 0);

    for (int kb = 0; kb < 32; kb++) {
        asm volatile("cp.async.wait_group 0;" ::: "memory");
        __syncthreads();
        if (kb < 31) issue((kb + 1) & 1, kb + 1);

        const uint32_t* As = sm + (kb & 1) * 8192;
        const uint32_t* Bs = As + 4096;

        #pragma unroll
        for (int kt2 = 0; kt2 < 2; kt2++) {
            uint4 Afh[4], Afl[4];
            uint2 Bfh[4], Bfl[4];
            const uint32_t* pa_ = &As[(kt2 * 8 + wm * 4) * 128 + lane * 4];
            #pragma unroll
            for (int i = 0; i < 4; i++) {
                Afh[i] = *(const uint4*)(pa_ + i * 128);
                Afl[i] = *(const uint4*)(pa_ + 2048 + i * 128);
            }
            const uint32_t* pb_ = &Bs[(kt2 * 16 + wn * 4) * 64 + lane * 2];
            #pragma unroll
            for (int i = 0; i < 4; i++) {
                Bfh[i] = *(const uint2*)(pb_ + i * 64);
                Bfl[i] = *(const uint2*)(pb_ + 2048 + i * 64);
            }
            #pragma unroll
            for (int mt = 0; mt < 4; mt++)
                #pragma unroll
                for (int nt = 0; nt < 4; nt++) {
                    mma16816(acc[mt][nt], (const uint32_t*)&Afh[mt], (const uint32_t*)&Bfh[nt]);
                    mma16816(acc[mt][nt], (const uint32_t*)&Afh[mt], (const uint32_t*)&Bfl[nt]);
                    mma16816(acc[mt][nt], (const uint32_t*)&Afl[mt], (const uint32_t*)&Bfh[nt]);
                }
        }
    }

    // epilogue
    #pragma unroll
    for (int mt = 0; mt < 4; mt++) {
        #pragma unroll
        for (int nt = 0; nt < 4; nt++) {
            const int m = m0 + wm * 64 + mt * 16 + (lane >> 2);
            const int n = n0 + wn * 32 + nt * 8 + ((lane & 3) << 1);  // even
            float* c = acc[mt][nt];
            const int b = m >> 11, t = m & 2047;
            const int h = n >> 6,  d = n & 63;
            const int bh = b * HH + h;
            if (which < 2) {
                const int i = d >> 1;
                #pragma unroll
                for (int rr = 0; rr < 2; rr++) {
                    const int tt = t + rr * 8;
                    const float2 cs = fc2[tt * 32 + i];
                    float o0 = c[rr*2] * cs.x - c[rr*2+1] * cs.y;
                    float o1 = c[rr*2] * cs.y + c[rr*2+1] * cs.x;
                    uint32_t lo, hi;
                    if (which == 0) {
                        hi = split_pair(o0 * 0.125f, o1 * 0.125f, lo);
                        const size_t qi = qfragidx(bh, tt, i);
                        qfh[qi] = hi; qfl[qi] = lo;
                    } else {
                        hi = split_pair(o0, o1, lo);
                        const size_t ki = kfragidx(bh, tt, i);
                        kfh[ki] = hi; kfl[ki] = lo;
                    }
                }
            } else {
                #pragma unroll
                for (int rr = 0; rr < 2; rr++) {
                    const int tt = t + rr * 8;
                    const int kt3 = tt >> 6, kpp = (tt & 63) >> 1, hf = tt & 1;
                    const int ks3 = kpp >> 3, kk3 = kpp & 7;
                    const int c3 = kk3 & 3, kh3 = kk3 >> 2;
                    #pragma unroll
                    for (int jj = 0; jj < 2; jj++) {
                        const int dd = d + jj;
                        const int slot = ((ks3 * 8 + (dd >> 3)) * 32 + (dd & 7) * 4 + c3) * 2 + kh3;
                        const size_t u32i = (size_t)bh * 65536 + kt3 * 2048 + slot;
                        const float v = c[rr * 2 + jj];
                        __nv_bfloat16 hb = __float2bfloat16_rn(v);
                        __nv_bfloat16 lb = __float2bfloat16_rn(v - __bfloat162float(hb));
                        ((uint16_t*)vfh)[u32i * 2 + hf] = *(uint16_t*)&hb;
                        ((uint16_t*)vfl)[u32i * 2 + hf] = *(uint16_t*)&lb;
                    }
                }
            }
        }
    }
}

// ---------------------------------------------------------------------------
// O-projection GEMM (A-perm x B-perm -> fp32 row-major out)
// ---------------------------------------------------------------------------
__global__ __launch_bounds__(256)
void gemm_o(const uint32_t* __restrict__ Ah, const uint32_t* __restrict__ Al,
            const uint32_t* __restrict__ Wh, const uint32_t* __restrict__ Wl,
            float* __restrict__ C) {
    extern __shared__ __align__(16) uint32_t sm[];

    const int tid  = threadIdx.x;
    const int lane = tid & 31;
    const int w    = tid >> 5;
    const int wm   = w & 1;
    const int wn   = w >> 1;
    const int m0   = blockIdx.y * 128;
    const int n0   = blockIdx.x * 128;
    const size_t abase = ((size_t)blockIdx.y * 32) * 2048;
    const size_t bbase = ((size_t)blockIdx.x * 32) * 2048;
    const uint32_t smaddr = smem_u32(sm);

    float acc[4][4][4];
    #pragma unroll
    for (int i = 0; i < 4; i++)
        #pragma unroll
        for (int j = 0; j < 4; j++)
            #pragma unroll
            for (int r = 0; r < 4; r++) acc[i][j][r] = 0.f;

    auto issue = [&](int st, int kb) {
        const uint32_t dbase = smaddr + (uint32_t)st * 32768u + tid * 32u;
        const size_t ko = (size_t)kb * 2048 + tid * 8;
        CP16(dbase,          Ah + abase + ko);
        CP16(dbase + 16,     Ah + abase + ko + 4);
        CP16(dbase + 8192,   Al + abase + ko);
        CP16(dbase + 8208,   Al + abase + ko + 4);
        CP16(dbase + 16384,  Wh + bbase + ko);
        CP16(dbase + 16400,  Wh + bbase + ko + 4);
        CP16(dbase + 24576,  Wl + bbase + ko);
        CP16(dbase + 24592,  Wl + bbase + ko + 4);
        asm volatile("cp.async.commit_group;" ::: "memory");
    };

    issue(0, 0);

    for (int kb = 0; kb < 32; kb++) {
        asm volatile("cp.async.wait_group 0;" ::: "memory");
        __syncthreads();
        if (kb < 31) issue((kb + 1) & 1, kb + 1);

        const uint32_t* As = sm + (kb & 1) * 8192;
        const uint32_t* Bs = As + 4096;

        #pragma unroll
        for (int kt2 = 0; kt2 < 2; kt2++) {
            uint4 Afh[4], Afl[4];
            uint2 Bfh[4], Bfl[4];
            const uint32_t* pa_ = &As[(kt2 * 8 + wm * 4) * 128 + lane * 4];
            #pragma unroll
            for (int i = 0; i < 4; i++) {
                Afh[i] = *(const uint4*)(pa_ + i * 128);
                Afl[i] = *(const uint4*)(pa_ + 2048 + i * 128);
            }
            const uint32_t* pb_ = &Bs[(kt2 * 16 + wn * 4) * 64 + lane * 2];
            #pragma unroll
            for (int i = 0; i < 4; i++) {
                Bfh[i] = *(const uint2*)(pb_ + i * 64);
                Bfl[i] = *(const uint2*)(pb_ + 2048 + i * 64);
            }
            #pragma unroll
            for (int mt = 0; mt < 4; mt++)
                #pragma unroll
                for (int nt = 0; nt < 4; nt++) {
                    mma16816(acc[mt][nt], (const uint32_t*)&Afh[mt], (const uint32_t*)&Bfh[nt]);
                    mma16816(acc[mt][nt], (const uint32_t*)&Afh[mt], (const uint32_t*)&Bfl[nt]);
                    mma16816(acc[mt][nt], (const uint32_t*)&Afl[mt], (const uint32_t*)&Bfh[nt]);
                }
        }
    }

    #pragma unroll
    for (int mt = 0; mt < 4; mt++) {
        #pragma unroll
        for (int nt = 0; nt < 4; nt++) {
            const int m = m0 + wm * 64 + mt * 16 + (lane >> 2);
            const int n = n0 + wn * 32 + nt * 8 + ((lane & 3) << 1);
            const float* c = acc[mt][nt];
            *(float2*)&C[(size_t)m * 1024 + n]       = make_float2(c[0], c[1]);
            *(float2*)&C[(size_t)(m + 8) * 1024 + n] = make_float2(c[2], c[3]);
        }
    }
}

// ---------------------------------------------------------------------------
// Tensor-core flash attention (mma.sync, causal). 128 q/block, 8 warps x 16 rows.
// ---------------------------------------------------------------------------
__global__ __launch_bounds__(256)
void attn_mma(const uint32_t* __restrict__ qfh, const uint32_t* __restrict__ qfl,
              const uint32_t* __restrict__ kfh, const uint32_t* __restrict__ kfl,
              const uint32_t* __restrict__ vfh, const uint32_t* __restrict__ vfl,
              uint32_t* __restrict__ aoh, uint32_t* __restrict__ aol) {
    extern __shared__ __align__(16) uint32_t sm[];   // 2 stages x 8192 u32 = 64KB
    const int bh = blockIdx.y;
    const int b  = bh >> 4, hhd = bh & 15;
    const int q0 = blockIdx.x * 128;
    const int tid = threadIdx.x;
    const int lane = tid & 31;
    const int w = tid >> 5;
    const uint32_t smaddr = smem_u32(sm);
    const size_t hbase = (size_t)bh * 65536;

    uint4 qfh_r[4], qfl_r[4];
    {
        const size_t qb = hbase + (size_t)blockIdx.x * 4096;
        #pragma unroll
        for (int ks = 0; ks < 4; ks++) {
            const size_t o = qb + ((w * 4 + ks) * 32 + lane) * 4;
            qfh_r[ks] = *(const uint4*)&qfh[o];
            qfl_r[ks] = *(const uint4*)&qfl[o];
        }
    }

    float oacc[8][4];
    #pragma unroll
    for (int dt = 0; dt < 8; dt++)
        #pragma unroll
        for (int r = 0; r < 4; r++) oacc[dt][r] = 0.f;
    float mr0 = -1e30f, mr1 = -1e30f, lr0 = 0.f, lr1 = 0.f;

    const int r0 = q0 + w * 16;
    const int ntiles = blockIdx.x * 2 + 2;

    auto issue = [&](int st, int kt) {
        const uint32_t dbase = smaddr + (uint32_t)st * 32768u + tid * 32u;
        const size_t ko = hbase + (size_t)kt * 2048 + tid * 8;
        CP16(dbase,          kfh + ko);
        CP16(dbase + 16,     kfh + ko + 4);
        CP16(dbase + 8192,   kfl + ko);
        CP16(dbase + 8208,   kfl + ko + 4);
        CP16(dbase + 16384,  vfh + ko);
        CP16(dbase + 16400,  vfh + ko + 4);
        CP16(dbase + 24576,  vfl + ko);
        CP16(dbase + 24592,  vfl + ko + 4);
        asm volatile("cp.async.commit_group;" ::: "memory");
    };

    issue(0, 0);

    for (int kt = 0; kt < ntiles; kt++) {
        const int kt0 = kt * 64;
        asm volatile("cp.async.wait_group 0;" ::: "memory");
        __syncthreads();
        if (kt + 1 < ntiles) issue((kt + 1) & 1, kt + 1);

        const uint32_t* S = sm + (kt & 1) * 8192;

        if (kt0 <= r0 + 15) {
            float sacc[8][4];
            #pragma unroll
            for (int nt = 0; nt < 8; nt++) {
                #pragma unroll
                for (int r = 0; r < 4; r++) sacc[nt][r] = 0.f;
                #pragma unroll
                for (int ks = 0; ks < 4; ks++) {
                    uint2 kbh = *(const uint2*)&S[((ks * 8 + nt) * 32 + lane) * 2];
                    uint2 kbl = *(const uint2*)&S[2048 + ((ks * 8 + nt) * 32 + lane) * 2];
                    mma16816(sacc[nt], (const uint32_t*)&qfh_r[ks], (const uint32_t*)&kbh);
                    mma16816(sacc[nt], (const uint32_t*)&qfh_r[ks], (const uint32_t*)&kbl);
                    mma16816(sacc[nt], (const uint32_t*)&qfl_r[ks], (const uint32_t*)&kbh);
                }
            }
            if (kt0 + 63 > r0) {
                const int colb = kt0 + ((lane & 3) << 1);
                const int rowb = r0 + (lane >> 2);
                #pragma unroll
                for (int nt = 0; nt < 8; nt++) {
                    #pragma unroll
                    for (int r = 0; r < 4; r++) {
                        const int col = colb + nt * 8 + (r & 1);
                        const int row = rowb + ((r >> 1) << 3);
                        if (col > row) sacc[nt][r] = -1e30f;
                    }
                }
            }
            float mx0 = -1e30f, mx1 = -1e30f;
            #pragma unroll
            for (int nt = 0; nt < 8; nt++) {
                mx0 = fmaxf(mx0, fmaxf(sacc[nt][0], sacc[nt][1]));
                mx1 = fmaxf(mx1, fmaxf(sacc[nt][2], sacc[nt][3]));
            }
            mx0 = fmaxf(mx0, __shfl_xor_sync(0xffffffffu, mx0, 1));
            mx0 = fmaxf(mx0, __shfl_xor_sync(0xffffffffu, mx0, 2));
            mx1 = fmaxf(mx1, __shfl_xor_sync(0xffffffffu, mx1, 1));
            mx1 = fmaxf(mx1, __shfl_xor_sync(0xffffffffu, mx1, 2));
            const float mn0 = fmaxf(mr0, mx0);
            const float mn1 = fmaxf(mr1, mx1);
            const float corr0 = __expf(mr0 - mn0);
            const float corr1 = __expf(mr1 - mn1);
            mr0 = mn0; mr1 = mn1;
            float s0 = 0.f, s1 = 0.f;
            #pragma unroll
            for (int nt = 0; nt < 8; nt++) {
                sacc[nt][0] = __expf(sacc[nt][0] - mn0);
                sacc[nt][1] = __expf(sacc[nt][1] - mn0);
                sacc[nt][2] = __expf(sacc[nt][2] - mn1);
                sacc[nt][3] = __expf(sacc[nt][3] - mn1);
                s0 += sacc[nt][0] + sacc[nt][1];
                s1 += sacc[nt][2] + sacc[nt][3];
            }
            lr0 = lr0 * corr0 + s0;
            lr1 = lr1 * corr1 + s1;
            #pragma unroll
            for (int dt = 0; dt < 8; dt++) {
                oacc[dt][0] *= corr0; oacc[dt][1] *= corr0;
                oacc[dt][2] *= corr1; oacc[dt][3] *= corr1;
            }
            uint32_t pah[4][4], pal[4][4];
            #pragma unroll
            for (int ksp = 0; ksp < 4; ksp++) {
                pah[ksp][0] = split_pair(sacc[2*ksp][0],   sacc[2*ksp][1],   pal[ksp][0]);
                pah[ksp][1] = split_pair(sacc[2*ksp][2],   sacc[2*ksp][3],   pal[ksp][1]);
                pah[ksp][2] = split_pair(sacc[2*ksp+1][0], sacc[2*ksp+1][1], pal[ksp][2]);
                pah[ksp][3] = split_pair(sacc[2*ksp+1][2], sacc[2*ksp+1][3], pal[ksp][3]);
            }
            #pragma unroll
            for (int dt = 0; dt < 8; dt++) {
                #pragma unroll
                for (int ksp = 0; ksp < 4; ksp++) {
                    uint2 vbh = *(const uint2*)&S[4096 + ((ksp * 8 + dt) * 32 + lane) * 2];
                    uint2 vbl = *(const uint2*)&S[6144 + ((ksp * 8 + dt) * 32 + lane) * 2];
                    mma16816(oacc[dt], pah[ksp], (const uint32_t*)&vbh);
                    mma16816(oacc[dt], pal[ksp], (const uint32_t*)&vbh);
                    mma16816(oacc[dt], pah[ksp], (const uint32_t*)&vbl);
                }
            }
        }
    }

    lr0 += __shfl_xor_sync(0xffffffffu, lr0, 1);
    lr0 += __shfl_xor_sync(0xffffffffu, lr0, 2);
    lr1 += __shfl_xor_sync(0xffffffffu, lr1, 1);
    lr1 += __shfl_xor_sync(0xffffffffu, lr1, 2);
    const float inv0 = 1.f / lr0;
    const float inv1 = 1.f / lr1;
    const int t0 = r0 + (lane >> 2);
    const int t1 = t0 + 8;
    #pragma unroll
    for (int dt = 0; dt < 8; dt++) {
        const int kp = hhd * 32 + dt * 4 + (lane & 3);
        uint32_t lo;
        uint32_t hi = split_pair(oacc[dt][0] * inv0, oacc[dt][1] * inv0, lo);
        const size_t i0 = apermidx(b * TT + t0, kp);
        aoh[i0] = hi; aol[i0] = lo;
        hi = split_pair(oacc[dt][2] * inv1, oacc[dt][3] * inv1, lo);
        const size_t i1 = apermidx(b * TT + t1, kp);
        aoh[i1] = hi; aol[i1] = lo;
    }
}

// ---------------------------------------------------------------------------
extern "C" void kernel_launch(void* const* d_in, const int* in_sizes, int n_in,
                              void* d_out, int out_size) {
    const float* x  = (const float*)d_in[0];
    const float* wq = (const float*)d_in[1];
    const float* wk = (const float*)d_in[2];
    const float* wv = (const float*)d_in[3];
    const float* wo = (const float*)d_in[4];
    const float* fc = (const float*)d_in[5];
    float* out = (float*)d_out;

    uint32_t *qfhp, *qflp, *kfhp, *kflp, *vfhp, *vflp;
    uint32_t *xhp, *xlp, *aohp, *aolp;
    uint32_t *wqhp, *wqlp, *wkhp, *wklp, *wvhp, *wvlp, *wohp, *wolp;
    cudaGetSymbolAddress((void**)&qfhp, g_qfh);
    cudaGetSymbolAddress((void**)&qflp, g_qfl);
    cudaGetSymbolAddress((void**)&kfhp, g_kfh);
    cudaGetSymbolAddress((void**)&kflp, g_kfl);
    cudaGetSymbolAddress((void**)&vfhp, g_vfh);
    cudaGetSymbolAddress((void**)&vflp, g_vfl);
    cudaGetSymbolAddress((void**)&xhp, g_xh);
    cudaGetSymbolAddress((void**)&xlp, g_xl);
    cudaGetSymbolAddress((void**)&aohp, g_aoh);
    cudaGetSymbolAddress((void**)&aolp, g_aol);
    cudaGetSymbolAddress((void**)&wqhp, g_wqh);
    cudaGetSymbolAddress((void**)&wqlp, g_wql);
    cudaGetSymbolAddress((void**)&wkhp, g_wkh);
    cudaGetSymbolAddress((void**)&wklp, g_wkl);
    cudaGetSymbolAddress((void**)&wvhp, g_wvh);
    cudaGetSymbolAddress((void**)&wvlp, g_wvl);
    cudaGetSymbolAddress((void**)&wohp, g_woh);
    cudaGetSymbolAddress((void**)&wolp, g_wol);

    const int DYNSZ = 65536;
    cudaFuncSetAttribute(gemm_qkv, cudaFuncAttributeMaxDynamicSharedMemorySize, DYNSZ);
    cudaFuncSetAttribute(gemm_o,   cudaFuncAttributeMaxDynamicSharedMemorySize, DYNSZ);
    cudaFuncSetAttribute(attn_mma, cudaFuncAttributeMaxDynamicSharedMemorySize, DYNSZ);

    const int xpairs = M_ROWS * 512;
    const int wpairs = DD * 512;
    split_permA<<<(xpairs + 255) / 256, 256>>>((const float2*)x, xhp, xlp, xpairs);
    dim3 sgrid((wpairs + 255) / 256, 4);
    split_permB4<<<sgrid, 256>>>((const float2*)wq, (const float2*)wk,
                                 (const float2*)wv, (const float2*)wo,
                                 wqhp, wqlp, wkhp, wklp, wvhp, wvlp, wohp, wolp,
                                 wpairs);

    dim3 qkvgrid(24, M_ROWS / 128);   // (24, 32)
    gemm_qkv<<<qkvgrid, 256, DYNSZ>>>(xhp, xlp, wqhp, wqlp, wkhp, wklp, wvhp, wvlp,
                                      (const float2*)fc, qfhp, qflp, kfhp, kflp,
                                      vfhp, vflp);

    dim3 agrid(TT / 128, BB * HH);    // (16, 32)
    attn_mma<<<agrid, 256, DYNSZ>>>(qfhp, qflp, kfhp, kflp, vfhp, vflp, aohp, aolp);

    dim3 ogrid(DD / 128, M_ROWS / 128);
    gemm_o<<<ogrid, 256, DYNSZ>>>(aohp, aolp, wohp, wolp, out);
}

// round 9
// speedup vs baseline: 4.6685x; 1.1482x over previous
#include <cuda_runtime.h>
#include <cuda_bf16.h>
#include <cstdint>

#define BB 2
#define TT 2048
#define DD 1024
#define HH 16
#define HD 64
#define M_ROWS (BB*TT)   // 4096

// ---------------------------------------------------------------------------
// Device scratch (allocation-free). All tensor-op operands live in
// mma-fragment-image order in global memory.
// ---------------------------------------------------------------------------
__device__ uint32_t g_qfh[BB*HH*16*4096];    // Q A-frag image per 128-row block
__device__ uint32_t g_qfl[BB*HH*16*4096];
__device__ uint32_t g_kfh[BB*HH*32*2048];    // K B-frag image per 64-key tile
__device__ uint32_t g_kfl[BB*HH*32*2048];
__device__ uint32_t g_vfh[BB*HH*32*2048];    // V B-frag image per 64-key tile
__device__ uint32_t g_vfl[BB*HH*32*2048];
__device__ uint32_t g_xh[M_ROWS*512];        // x, A-perm
__device__ uint32_t g_xl[M_ROWS*512];
__device__ uint32_t g_wqh[DD*512], g_wql[DD*512];   // weights, B-perm
__device__ uint32_t g_wkh[DD*512], g_wkl[DD*512];
__device__ uint32_t g_wvh[DD*512], g_wvl[DD*512];
__device__ uint32_t g_woh[DD*512], g_wol[DD*512];
__device__ uint32_t g_aoh[M_ROWS*512];       // attn out, A-perm
__device__ uint32_t g_aol[M_ROWS*512];

// ---------------------------------------------------------------------------
// helpers
// ---------------------------------------------------------------------------
__device__ __forceinline__ uint32_t smem_u32(const void* p) {
    return (uint32_t)__cvta_generic_to_shared(p);
}

#define CP16(d, s) asm volatile("cp.async.cg.shared.global [%0], [%1], 16;" \
                                :: "r"(d), "l"(s) : "memory")

__device__ __forceinline__ void mma16816(float* c, const uint32_t* a, const uint32_t* b) {
    asm volatile(
        "mma.sync.aligned.m16n8k16.row.col.f32.bf16.bf16.f32 "
        "{%0,%1,%2,%3}, {%4,%5,%6,%7}, {%8,%9}, {%0,%1,%2,%3};"
        : "+f"(c[0]), "+f"(c[1]), "+f"(c[2]), "+f"(c[3])
        : "r"(a[0]), "r"(a[1]), "r"(a[2]), "r"(a[3]), "r"(b[0]), "r"(b[1]));
}

__device__ __forceinline__ uint32_t split_pair(float a, float b, uint32_t& lo) {
    __nv_bfloat162 h = __floats2bfloat162_rn(a, b);
    float ra = a - __bfloat162float(h.x);
    float rb = b - __bfloat162float(h.y);
    __nv_bfloat162 l = __floats2bfloat162_rn(ra, rb);
    lo = *reinterpret_cast<uint32_t*>(&l);
    return *reinterpret_cast<uint32_t*>(&h);
}

// A-perm index: (m row 0..4095, kp pair 0..511) -> fragment-image slot
__device__ __forceinline__ size_t apermidx(int m, int kp) {
    const int mb = m >> 7, r = m & 127;
    const int kb = kp >> 4, kr = kp & 15;
    const int kt = kr >> 3, khalf = (kr >> 2) & 1, j = kr & 3;
    const int tile = kt * 8 + (r >> 4);
    const int lane = (r & 7) * 4 + j;
    const int areg = ((r >> 3) & 1) | (khalf << 1);
    return ((size_t)(mb * 32 + kb)) * 2048 + tile * 128 + lane * 4 + areg;
}
// B-perm index: (n row, kp pair) -> fragment-image slot
__device__ __forceinline__ size_t bpermidx(int n, int kp) {
    const int nb = n >> 7, r = n & 127;
    const int kb = kp >> 4, kr = kp & 15;
    const int kt = kr >> 3, khalf = (kr >> 2) & 1, j = kr & 3;
    return ((size_t)(nb * 32 + kb)) * 2048 +
           (kt * 16 + (r >> 3)) * 64 + ((r & 7) * 4 + j) * 2 + khalf;
}
// Q-frag slot for (bh, t, pair i)
__device__ __forceinline__ size_t qfragidx(int bh, int t, int i) {
    const int ks = i >> 3, kk2 = i & 7;
    const int c2 = kk2 & 3, khalf = kk2 >> 2;
    const int row = t & 127, qb = t >> 7;
    const int wq = row >> 4, wrow = row & 15;
    const int areg = ((wrow >> 3) & 1) | (khalf << 1);
    return (size_t)bh * 65536 + qb * 4096 +
           ((wq * 4 + ks) * 32 + (wrow & 7) * 4 + c2) * 4 + areg;
}
// K-frag slot for (bh, t, pair i)
__device__ __forceinline__ size_t kfragidx(int bh, int t, int i) {
    const int ks = i >> 3, kk2 = i & 7;
    const int c2 = kk2 & 3, khalf = kk2 >> 2;
    const int key = t & 63, ktile = t >> 6;
    return (size_t)bh * 65536 + ktile * 2048 +
           ((ks * 8 + (key >> 3)) * 32 + (key & 7) * 4 + c2) * 2 + khalf;
}

// ---------------------------------------------------------------------------
// splits
// ---------------------------------------------------------------------------
__global__ void split_permA(const float2* __restrict__ src,
                            uint32_t* __restrict__ dh, uint32_t* __restrict__ dl,
                            int total) {
    int i = blockIdx.x * blockDim.x + threadIdx.x;
    if (i >= total) return;
    float2 v = src[i];
    uint32_t lo, hi = split_pair(v.x, v.y, lo);
    const size_t idx = apermidx(i >> 9, i & 511);
    dh[idx] = hi; dl[idx] = lo;
}
__global__ void split_permB4(const float2* __restrict__ s0, const float2* __restrict__ s1,
                             const float2* __restrict__ s2, const float2* __restrict__ s3,
                             uint32_t* __restrict__ h0, uint32_t* __restrict__ l0,
                             uint32_t* __restrict__ h1, uint32_t* __restrict__ l1,
                             uint32_t* __restrict__ h2, uint32_t* __restrict__ l2,
                             uint32_t* __restrict__ h3, uint32_t* __restrict__ l3,
                             int total) {
    int i = blockIdx.x * blockDim.x + threadIdx.x;
    if (i >= total) return;
    const int which = blockIdx.y;
    const float2* src = which == 0 ? s0 : which == 1 ? s1 : which == 2 ? s2 : s3;
    uint32_t* dh = which == 0 ? h0 : which == 1 ? h1 : which == 2 ? h2 : h3;
    uint32_t* dl = which == 0 ? l0 : which == 1 ? l1 : which == 2 ? l2 : l3;
    float2 v = src[i];
    uint32_t lo, hi = split_pair(v.x, v.y, lo);
    const size_t idx = bpermidx(i >> 9, i & 511);
    dh[idx] = hi; dl[idx] = lo;
}

// ---------------------------------------------------------------------------
// Fused QKV GEMM (grid.x = 24: 8 n-blocks x {Q,K,V}). cp.async mainloop.
// ---------------------------------------------------------------------------
__global__ __launch_bounds__(256)
void gemm_qkv(const uint32_t* __restrict__ Ah, const uint32_t* __restrict__ Al,
              const uint32_t* __restrict__ Wqh, const uint32_t* __restrict__ Wql,
              const uint32_t* __restrict__ Wkh, const uint32_t* __restrict__ Wkl,
              const uint32_t* __restrict__ Wvh, const uint32_t* __restrict__ Wvl,
              const float2* __restrict__ fc2,
              uint32_t* __restrict__ qfh, uint32_t* __restrict__ qfl,
              uint32_t* __restrict__ kfh, uint32_t* __restrict__ kfl,
              uint32_t* __restrict__ vfh, uint32_t* __restrict__ vfl) {
    extern __shared__ __align__(16) uint32_t sm[];   // 64KB

    const int which = blockIdx.x >> 3;               // 0=Q 1=K 2=V
    const int nblk  = blockIdx.x & 7;
    const uint32_t* Wh = which == 0 ? Wqh : which == 1 ? Wkh : Wvh;
    const uint32_t* Wl = which == 0 ? Wql : which == 1 ? Wkl : Wvl;

    const int tid  = threadIdx.x;
    const int lane = tid & 31;
    const int w    = tid >> 5;
    const int wm   = w & 1;
    const int wn   = w >> 1;
    const int m0   = blockIdx.y * 128;
    const int n0   = nblk * 128;
    const size_t abase = ((size_t)blockIdx.y * 32) * 2048;
    const size_t bbase = ((size_t)nblk * 32) * 2048;
    const uint32_t smaddr = smem_u32(sm);

    float acc[4][4][4];
    #pragma unroll
    for (int i = 0; i < 4; i++)
        #pragma unroll
        for (int j = 0; j < 4; j++)
            #pragma unroll
            for (int r = 0; r < 4; r++) acc[i][j][r] = 0.f;

    auto issue = [&](int st, int kb) {
        const uint32_t dbase = smaddr + (uint32_t)st * 32768u + tid * 32u;
        const size_t ko = (size_t)kb * 2048 + tid * 8;
        CP16(dbase,          Ah + abase + ko);
        CP16(dbase + 16,     Ah + abase + ko + 4);
        CP16(dbase + 8192,   Al + abase + ko);
        CP16(dbase + 8208,   Al + abase + ko + 4);
        CP16(dbase + 16384,  Wh + bbase + ko);
        CP16(dbase + 16400,  Wh + bbase + ko + 4);
        CP16(dbase + 24576,  Wl + bbase + ko);
        CP16(dbase + 24592,  Wl + bbase + ko + 4);
        asm volatile("cp.async.commit_group;" ::: "memory");
    };

    issue(0, 0);

    for (int kb = 0; kb < 32; kb++) {
        asm volatile("cp.async.wait_group 0;" ::: "memory");
        __syncthreads();
        if (kb < 31) issue((kb + 1) & 1, kb + 1);

        const uint32_t* As = sm + (kb & 1) * 8192;
        const uint32_t* Bs = As + 4096;

        #pragma unroll
        for (int kt2 = 0; kt2 < 2; kt2++) {
            uint4 Afh[4], Afl[4];
            uint2 Bfh[4], Bfl[4];
            const uint32_t* pa_ = &As[(kt2 * 8 + wm * 4) * 128 + lane * 4];
            #pragma unroll
            for (int i = 0; i < 4; i++) {
                Afh[i] = *(const uint4*)(pa_ + i * 128);
                Afl[i] = *(const uint4*)(pa_ + 2048 + i * 128);
            }
            const uint32_t* pb_ = &Bs[(kt2 * 16 + wn * 4) * 64 + lane * 2];
            #pragma unroll
            for (int i = 0; i < 4; i++) {
                Bfh[i] = *(const uint2*)(pb_ + i * 64);
                Bfl[i] = *(const uint2*)(pb_ + 2048 + i * 64);
            }
            #pragma unroll
            for (int mt = 0; mt < 4; mt++)
                #pragma unroll
                for (int nt = 0; nt < 4; nt++) {
                    mma16816(acc[mt][nt], (const uint32_t*)&Afh[mt], (const uint32_t*)&Bfh[nt]);
                    mma16816(acc[mt][nt], (const uint32_t*)&Afh[mt], (const uint32_t*)&Bfl[nt]);
                    mma16816(acc[mt][nt], (const uint32_t*)&Afl[mt], (const uint32_t*)&Bfh[nt]);
                }
        }
    }

    // epilogue
    #pragma unroll
    for (int mt = 0; mt < 4; mt++) {
        #pragma unroll
        for (int nt = 0; nt < 4; nt++) {
            const int m = m0 + wm * 64 + mt * 16 + (lane >> 2);
            const int n = n0 + wn * 32 + nt * 8 + ((lane & 3) << 1);  // even
            float* c = acc[mt][nt];
            const int b = m >> 11, t = m & 2047;
            const int h = n >> 6,  d = n & 63;
            const int bh = b * HH + h;
            if (which < 2) {
                const int i = d >> 1;
                #pragma unroll
                for (int rr = 0; rr < 2; rr++) {
                    const int tt = t + rr * 8;
                    const float2 cs = fc2[tt * 32 + i];
                    float o0 = c[rr*2] * cs.x - c[rr*2+1] * cs.y;
                    float o1 = c[rr*2] * cs.y + c[rr*2+1] * cs.x;
                    uint32_t lo, hi;
                    if (which == 0) {
                        hi = split_pair(o0 * 0.125f, o1 * 0.125f, lo);
                        const size_t qi = qfragidx(bh, tt, i);
                        qfh[qi] = hi; qfl[qi] = lo;
                    } else {
                        hi = split_pair(o0, o1, lo);
                        const size_t ki = kfragidx(bh, tt, i);
                        kfh[ki] = hi; kfl[ki] = lo;
                    }
                }
            } else {
                #pragma unroll
                for (int rr = 0; rr < 2; rr++) {
                    const int tt = t + rr * 8;
                    const int kt3 = tt >> 6, kpp = (tt & 63) >> 1, hf = tt & 1;
                    const int ks3 = kpp >> 3, kk3 = kpp & 7;
                    const int c3 = kk3 & 3, kh3 = kk3 >> 2;
                    #pragma unroll
                    for (int jj = 0; jj < 2; jj++) {
                        const int dd = d + jj;
                        const int slot = ((ks3 * 8 + (dd >> 3)) * 32 + (dd & 7) * 4 + c3) * 2 + kh3;
                        const size_t u32i = (size_t)bh * 65536 + kt3 * 2048 + slot;
                        const float v = c[rr * 2 + jj];
                        __nv_bfloat16 hb = __float2bfloat16_rn(v);
                        __nv_bfloat16 lb = __float2bfloat16_rn(v - __bfloat162float(hb));
                        ((uint16_t*)vfh)[u32i * 2 + hf] = *(uint16_t*)&hb;
                        ((uint16_t*)vfl)[u32i * 2 + hf] = *(uint16_t*)&lb;
                    }
                }
            }
        }
    }
}

// ---------------------------------------------------------------------------
// O-projection GEMM (A-perm x B-perm -> fp32 row-major out)
// ---------------------------------------------------------------------------
__global__ __launch_bounds__(256)
void gemm_o(const uint32_t* __restrict__ Ah, const uint32_t* __restrict__ Al,
            const uint32_t* __restrict__ Wh, const uint32_t* __restrict__ Wl,
            float* __restrict__ C) {
    extern __shared__ __align__(16) uint32_t sm[];

    const int tid  = threadIdx.x;
    const int lane = tid & 31;
    const int w    = tid >> 5;
    const int wm   = w & 1;
    const int wn   = w >> 1;
    const int m0   = blockIdx.y * 128;
    const int n0   = blockIdx.x * 128;
    const size_t abase = ((size_t)blockIdx.y * 32) * 2048;
    const size_t bbase = ((size_t)blockIdx.x * 32) * 2048;
    const uint32_t smaddr = smem_u32(sm);

    float acc[4][4][4];
    #pragma unroll
    for (int i = 0; i < 4; i++)
        #pragma unroll
        for (int j = 0; j < 4; j++)
            #pragma unroll
            for (int r = 0; r < 4; r++) acc[i][j][r] = 0.f;

    auto issue = [&](int st, int kb) {
        const uint32_t dbase = smaddr + (uint32_t)st * 32768u + tid * 32u;
        const size_t ko = (size_t)kb * 2048 + tid * 8;
        CP16(dbase,          Ah + abase + ko);
        CP16(dbase + 16,     Ah + abase + ko + 4);
        CP16(dbase + 8192,   Al + abase + ko);
        CP16(dbase + 8208,   Al + abase + ko + 4);
        CP16(dbase + 16384,  Wh + bbase + ko);
        CP16(dbase + 16400,  Wh + bbase + ko + 4);
        CP16(dbase + 24576,  Wl + bbase + ko);
        CP16(dbase + 24592,  Wl + bbase + ko + 4);
        asm volatile("cp.async.commit_group;" ::: "memory");
    };

    issue(0, 0);

    for (int kb = 0; kb < 32; kb++) {
        asm volatile("cp.async.wait_group 0;" ::: "memory");
        __syncthreads();
        if (kb < 31) issue((kb + 1) & 1, kb + 1);

        const uint32_t* As = sm + (kb & 1) * 8192;
        const uint32_t* Bs = As + 4096;

        #pragma unroll
        for (int kt2 = 0; kt2 < 2; kt2++) {
            uint4 Afh[4], Afl[4];
            uint2 Bfh[4], Bfl[4];
            const uint32_t* pa_ = &As[(kt2 * 8 + wm * 4) * 128 + lane * 4];
            #pragma unroll
            for (int i = 0; i < 4; i++) {
                Afh[i] = *(const uint4*)(pa_ + i * 128);
                Afl[i] = *(const uint4*)(pa_ + 2048 + i * 128);
            }
            const uint32_t* pb_ = &Bs[(kt2 * 16 + wn * 4) * 64 + lane * 2];
            #pragma unroll
            for (int i = 0; i < 4; i++) {
                Bfh[i] = *(const uint2*)(pb_ + i * 64);
                Bfl[i] = *(const uint2*)(pb_ + 2048 + i * 64);
            }
            #pragma unroll
            for (int mt = 0; mt < 4; mt++)
                #pragma unroll
                for (int nt = 0; nt < 4; nt++) {
                    mma16816(acc[mt][nt], (const uint32_t*)&Afh[mt], (const uint32_t*)&Bfh[nt]);
                    mma16816(acc[mt][nt], (const uint32_t*)&Afh[mt], (const uint32_t*)&Bfl[nt]);
                    mma16816(acc[mt][nt], (const uint32_t*)&Afl[mt], (const uint32_t*)&Bfh[nt]);
                }
        }
    }

    #pragma unroll
    for (int mt = 0; mt < 4; mt++) {
        #pragma unroll
        for (int nt = 0; nt < 4; nt++) {
            const int m = m0 + wm * 64 + mt * 16 + (lane >> 2);
            const int n = n0 + wn * 32 + nt * 8 + ((lane & 3) << 1);
            const float* c = acc[mt][nt];
            *(float2*)&C[(size_t)m * 1024 + n]       = make_float2(c[0], c[1]);
            *(float2*)&C[(size_t)(m + 8) * 1024 + n] = make_float2(c[2], c[3]);
        }
    }
}

// ---------------------------------------------------------------------------
// Tensor-core flash attention (mma.sync, causal). 1D grid, heavy-first:
// idx -> qi = 15 - idx/32, bh = idx%32. 2 CTAs/SM (Q-lo frags in smem).
// smem: [2 stages x 8192 u32][Q-lo 4096 u32] = 80KB.
// ---------------------------------------------------------------------------
__global__ __launch_bounds__(256, 2)
void attn_mma(const uint32_t* __restrict__ qfh, const uint32_t* __restrict__ qfl,
              const uint32_t* __restrict__ kfh, const uint32_t* __restrict__ kfl,
              const uint32_t* __restrict__ vfh, const uint32_t* __restrict__ vfl,
              uint32_t* __restrict__ aoh, uint32_t* __restrict__ aol) {
    extern __shared__ __align__(16) uint32_t sm[];
    const int qi = 15 - (blockIdx.x >> 5);
    const int bh = blockIdx.x & 31;
    const int b  = bh >> 4, hhd = bh & 15;
    const int q0 = qi * 128;
    const int tid = threadIdx.x;
    const int lane = tid & 31;
    const int w = tid >> 5;
    const uint32_t smaddr = smem_u32(sm);
    const size_t hbase = (size_t)bh * 65536;
    uint32_t* qlo_s = sm + 16384;

    // Q hi fragments in regs; Q lo staged to smem (keeps regs <= 128 for occ 2)
    uint4 qfh_r[4];
    {
        const size_t qb = hbase + (size_t)qi * 4096;
        #pragma unroll
        for (int ks = 0; ks < 4; ks++) {
            const size_t o = qb + ((w * 4 + ks) * 32 + lane) * 4;
            qfh_r[ks] = *(const uint4*)&qfh[o];
        }
        #pragma unroll
        for (int i = 0; i < 4; i++) {
            const int id = i * 1024 + tid * 4;
            *(uint4*)&qlo_s[id] = *(const uint4*)&qfl[qb + id];
        }
    }
    __syncthreads();

    float oacc[8][4];
    #pragma unroll
    for (int dt = 0; dt < 8; dt++)
        #pragma unroll
        for (int r = 0; r < 4; r++) oacc[dt][r] = 0.f;
    float mr0 = -1e30f, mr1 = -1e30f, lr0 = 0.f, lr1 = 0.f;

    const int r0 = q0 + w * 16;
    const int ntiles = qi * 2 + 2;

    auto issue = [&](int st, int kt) {
        const uint32_t dbase = smaddr + (uint32_t)st * 32768u + tid * 32u;
        const size_t ko = hbase + (size_t)kt * 2048 + tid * 8;
        CP16(dbase,          kfh + ko);
        CP16(dbase + 16,     kfh + ko + 4);
        CP16(dbase + 8192,   kfl + ko);
        CP16(dbase + 8208,   kfl + ko + 4);
        CP16(dbase + 16384,  vfh + ko);
        CP16(dbase + 16400,  vfh + ko + 4);
        CP16(dbase + 24576,  vfl + ko);
        CP16(dbase + 24592,  vfl + ko + 4);
        asm volatile("cp.async.commit_group;" ::: "memory");
    };

    issue(0, 0);

    for (int kt = 0; kt < ntiles; kt++) {
        const int kt0 = kt * 64;
        asm volatile("cp.async.wait_group 0;" ::: "memory");
        __syncthreads();
        if (kt + 1 < ntiles) issue((kt + 1) & 1, kt + 1);

        const uint32_t* S = sm + (kt & 1) * 8192;

        if (kt0 <= r0 + 15) {
            float sacc[8][4];
            #pragma unroll
            for (int nt = 0; nt < 8; nt++) {
                #pragma unroll
                for (int r = 0; r < 4; r++) sacc[nt][r] = 0.f;
                #pragma unroll
                for (int ks = 0; ks < 4; ks++) {
                    uint4 qlo = *(const uint4*)&qlo_s[((w * 4 + ks) * 32 + lane) * 4];
                    uint2 kbh = *(const uint2*)&S[((ks * 8 + nt) * 32 + lane) * 2];
                    uint2 kbl = *(const uint2*)&S[2048 + ((ks * 8 + nt) * 32 + lane) * 2];
                    mma16816(sacc[nt], (const uint32_t*)&qfh_r[ks], (const uint32_t*)&kbh);
                    mma16816(sacc[nt], (const uint32_t*)&qfh_r[ks], (const uint32_t*)&kbl);
                    mma16816(sacc[nt], (const uint32_t*)&qlo, (const uint32_t*)&kbh);
                }
            }
            if (kt0 + 63 > r0) {
                const int colb = kt0 + ((lane & 3) << 1);
                const int rowb = r0 + (lane >> 2);
                #pragma unroll
                for (int nt = 0; nt < 8; nt++) {
                    #pragma unroll
                    for (int r = 0; r < 4; r++) {
                        const int col = colb + nt * 8 + (r & 1);
                        const int row = rowb + ((r >> 1) << 3);
                        if (col > row) sacc[nt][r] = -1e30f;
                    }
                }
            }
            float mx0 = -1e30f, mx1 = -1e30f;
            #pragma unroll
            for (int nt = 0; nt < 8; nt++) {
                mx0 = fmaxf(mx0, fmaxf(sacc[nt][0], sacc[nt][1]));
                mx1 = fmaxf(mx1, fmaxf(sacc[nt][2], sacc[nt][3]));
            }
            mx0 = fmaxf(mx0, __shfl_xor_sync(0xffffffffu, mx0, 1));
            mx0 = fmaxf(mx0, __shfl_xor_sync(0xffffffffu, mx0, 2));
            mx1 = fmaxf(mx1, __shfl_xor_sync(0xffffffffu, mx1, 1));
            mx1 = fmaxf(mx1, __shfl_xor_sync(0xffffffffu, mx1, 2));
            const float mn0 = fmaxf(mr0, mx0);
            const float mn1 = fmaxf(mr1, mx1);
            const float corr0 = __expf(mr0 - mn0);
            const float corr1 = __expf(mr1 - mn1);
            mr0 = mn0; mr1 = mn1;
            float s0 = 0.f, s1 = 0.f;
            #pragma unroll
            for (int nt = 0; nt < 8; nt++) {
                sacc[nt][0] = __expf(sacc[nt][0] - mn0);
                sacc[nt][1] = __expf(sacc[nt][1] - mn0);
                sacc[nt][2] = __expf(sacc[nt][2] - mn1);
                sacc[nt][3] = __expf(sacc[nt][3] - mn1);
                s0 += sacc[nt][0] + sacc[nt][1];
                s1 += sacc[nt][2] + sacc[nt][3];
            }
            lr0 = lr0 * corr0 + s0;
            lr1 = lr1 * corr1 + s1;
            #pragma unroll
            for (int dt = 0; dt < 8; dt++) {
                oacc[dt][0] *= corr0; oacc[dt][1] *= corr0;
                oacc[dt][2] *= corr1; oacc[dt][3] *= corr1;
            }
            uint32_t pah[4][4], pal[4][4];
            #pragma unroll
            for (int ksp = 0; ksp < 4; ksp++) {
                pah[ksp][0] = split_pair(sacc[2*ksp][0],   sacc[2*ksp][1],   pal[ksp][0]);
                pah[ksp][1] = split_pair(sacc[2*ksp][2],   sacc[2*ksp][3],   pal[ksp][1]);
                pah[ksp][2] = split_pair(sacc[2*ksp+1][0], sacc[2*ksp+1][1], pal[ksp][2]);
                pah[ksp][3] = split_pair(sacc[2*ksp+1][2], sacc[2*ksp+1][3], pal[ksp][3]);
            }
            #pragma unroll
            for (int dt = 0; dt < 8; dt++) {
                #pragma unroll
                for (int ksp = 0; ksp < 4; ksp++) {
                    uint2 vbh = *(const uint2*)&S[4096 + ((ksp * 8 + dt) * 32 + lane) * 2];
                    uint2 vbl = *(const uint2*)&S[6144 + ((ksp * 8 + dt) * 32 + lane) * 2];
                    mma16816(oacc[dt], pah[ksp], (const uint32_t*)&vbh);
                    mma16816(oacc[dt], pal[ksp], (const uint32_t*)&vbh);
                    mma16816(oacc[dt], pah[ksp], (const uint32_t*)&vbl);
                }
            }
        }
    }

    lr0 += __shfl_xor_sync(0xffffffffu, lr0, 1);
    lr0 += __shfl_xor_sync(0xffffffffu, lr0, 2);
    lr1 += __shfl_xor_sync(0xffffffffu, lr1, 1);
    lr1 += __shfl_xor_sync(0xffffffffu, lr1, 2);
    const float inv0 = 1.f / lr0;
    const float inv1 = 1.f / lr1;
    const int t0 = r0 + (lane >> 2);
    const int t1 = t0 + 8;
    #pragma unroll
    for (int dt = 0; dt < 8; dt++) {
        const int kp = hhd * 32 + dt * 4 + (lane & 3);
        uint32_t lo;
        uint32_t hi = split_pair(oacc[dt][0] * inv0, oacc[dt][1] * inv0, lo);
        const size_t i0 = apermidx(b * TT + t0, kp);
        aoh[i0] = hi; aol[i0] = lo;
        hi = split_pair(oacc[dt][2] * inv1, oacc[dt][3] * inv1, lo);
        const size_t i1 = apermidx(b * TT + t1, kp);
        aoh[i1] = hi; aol[i1] = lo;
    }
}

// ---------------------------------------------------------------------------
extern "C" void kernel_launch(void* const* d_in, const int* in_sizes, int n_in,
                              void* d_out, int out_size) {
    const float* x  = (const float*)d_in[0];
    const float* wq = (const float*)d_in[1];
    const float* wk = (const float*)d_in[2];
    const float* wv = (const float*)d_in[3];
    const float* wo = (const float*)d_in[4];
    const float* fc = (const float*)d_in[5];
    float* out = (float*)d_out;

    uint32_t *qfhp, *qflp, *kfhp, *kflp, *vfhp, *vflp;
    uint32_t *xhp, *xlp, *aohp, *aolp;
    uint32_t *wqhp, *wqlp, *wkhp, *wklp, *wvhp, *wvlp, *wohp, *wolp;
    cudaGetSymbolAddress((void**)&qfhp, g_qfh);
    cudaGetSymbolAddress((void**)&qflp, g_qfl);
    cudaGetSymbolAddress((void**)&kfhp, g_kfh);
    cudaGetSymbolAddress((void**)&kflp, g_kfl);
    cudaGetSymbolAddress((void**)&vfhp, g_vfh);
    cudaGetSymbolAddress((void**)&vflp, g_vfl);
    cudaGetSymbolAddress((void**)&xhp, g_xh);
    cudaGetSymbolAddress((void**)&xlp, g_xl);
    cudaGetSymbolAddress((void**)&aohp, g_aoh);
    cudaGetSymbolAddress((void**)&aolp, g_aol);
    cudaGetSymbolAddress((void**)&wqhp, g_wqh);
    cudaGetSymbolAddress((void**)&wqlp, g_wql);
    cudaGetSymbolAddress((void**)&wkhp, g_wkh);
    cudaGetSymbolAddress((void**)&wklp, g_wkl);
    cudaGetSymbolAddress((void**)&wvhp, g_wvh);
    cudaGetSymbolAddress((void**)&wvlp, g_wvl);
    cudaGetSymbolAddress((void**)&wohp, g_woh);
    cudaGetSymbolAddress((void**)&wolp, g_wol);

    const int DYNSZ  = 65536;
    const int ADYNSZ = 81920;
    cudaFuncSetAttribute(gemm_qkv, cudaFuncAttributeMaxDynamicSharedMemorySize, DYNSZ);
    cudaFuncSetAttribute(gemm_o,   cudaFuncAttributeMaxDynamicSharedMemorySize, DYNSZ);
    cudaFuncSetAttribute(attn_mma, cudaFuncAttributeMaxDynamicSharedMemorySize, ADYNSZ);

    const int xpairs = M_ROWS * 512;
    const int wpairs = DD * 512;
    split_permA<<<(xpairs + 255) / 256, 256>>>((const float2*)x, xhp, xlp, xpairs);
    dim3 sgrid((wpairs + 255) / 256, 4);
    split_permB4<<<sgrid, 256>>>((const float2*)wq, (const float2*)wk,
                                 (const float2*)wv, (const float2*)wo,
                                 wqhp, wqlp, wkhp, wklp, wvhp, wvlp, wohp, wolp,
                                 wpairs);

    dim3 qkvgrid(24, M_ROWS / 128);   // (24, 32)
    gemm_qkv<<<qkvgrid, 256, DYNSZ>>>(xhp, xlp, wqhp, wqlp, wkhp, wklp, wvhp, wvlp,
                                      (const float2*)fc, qfhp, qflp, kfhp, kflp,
                                      vfhp, vflp);

    attn_mma<<<512, 256, ADYNSZ>>>(qfhp, qflp, kfhp, kflp, vfhp, vflp, aohp, aolp);

    dim3 ogrid(DD / 128, M_ROWS / 128);
    gemm_o<<<ogrid, 256, DYNSZ>>>(aohp, aolp, wohp, wolp, out);
}

// round 10
// speedup vs baseline: 4.7785x; 1.0236x over previous
#include <cuda_runtime.h>
#include <cuda_bf16.h>
#include <cstdint>

#define BB 2
#define TT 2048
#define DD 1024
#define HH 16
#define HD 64
#define M_ROWS (BB*TT)   // 4096

// ---------------------------------------------------------------------------
// Device scratch (allocation-free). All tensor-op operands live in
// mma-fragment-image order in global memory.
// ---------------------------------------------------------------------------
__device__ uint32_t g_qfh[BB*HH*16*4096];    // Q A-frag image per 128-row block
__device__ uint32_t g_qfl[BB*HH*16*4096];
__device__ uint32_t g_kfh[BB*HH*32*2048];    // K B-frag image per 64-key tile
__device__ uint32_t g_kfl[BB*HH*32*2048];
__device__ uint32_t g_vfh[BB*HH*32*2048];    // V B-frag image per 64-key tile
__device__ uint32_t g_vfl[BB*HH*32*2048];
__device__ uint32_t g_xh[M_ROWS*512];        // x, A-perm
__device__ uint32_t g_xl[M_ROWS*512];
__device__ uint32_t g_wqh[DD*512], g_wql[DD*512];   // weights, B-perm
__device__ uint32_t g_wkh[DD*512], g_wkl[DD*512];
__device__ uint32_t g_wvh[DD*512], g_wvl[DD*512];
__device__ uint32_t g_woh[DD*512], g_wol[DD*512];
__device__ uint32_t g_aoh[M_ROWS*512];       // attn out, A-perm
__device__ uint32_t g_aol[M_ROWS*512];

// ---------------------------------------------------------------------------
// helpers
// ---------------------------------------------------------------------------
__device__ __forceinline__ uint32_t smem_u32(const void* p) {
    return (uint32_t)__cvta_generic_to_shared(p);
}

#define CP16(d, s) asm volatile("cp.async.cg.shared.global [%0], [%1], 16;" \
                                :: "r"(d), "l"(s) : "memory")

__device__ __forceinline__ void mma16816(float* c, const uint32_t* a, const uint32_t* b) {
    asm volatile(
        "mma.sync.aligned.m16n8k16.row.col.f32.bf16.bf16.f32 "
        "{%0,%1,%2,%3}, {%4,%5,%6,%7}, {%8,%9}, {%0,%1,%2,%3};"
        : "+f"(c[0]), "+f"(c[1]), "+f"(c[2]), "+f"(c[3])
        : "r"(a[0]), "r"(a[1]), "r"(a[2]), "r"(a[3]), "r"(b[0]), "r"(b[1]));
}

__device__ __forceinline__ float ex2f(float x) {
    float y; asm("ex2.approx.f32 %0, %1;" : "=f"(y) : "f"(x)); return y;
}

__device__ __forceinline__ uint32_t split_pair(float a, float b, uint32_t& lo) {
    __nv_bfloat162 h = __floats2bfloat162_rn(a, b);
    float ra = a - __bfloat162float(h.x);
    float rb = b - __bfloat162float(h.y);
    __nv_bfloat162 l = __floats2bfloat162_rn(ra, rb);
    lo = *reinterpret_cast<uint32_t*>(&l);
    return *reinterpret_cast<uint32_t*>(&h);
}

// A-perm index: (m row 0..4095, kp pair 0..511) -> fragment-image slot
__device__ __forceinline__ size_t apermidx(int m, int kp) {
    const int mb = m >> 7, r = m & 127;
    const int kb = kp >> 4, kr = kp & 15;
    const int kt = kr >> 3, khalf = (kr >> 2) & 1, j = kr & 3;
    const int tile = kt * 8 + (r >> 4);
    const int lane = (r & 7) * 4 + j;
    const int areg = ((r >> 3) & 1) | (khalf << 1);
    return ((size_t)(mb * 32 + kb)) * 2048 + tile * 128 + lane * 4 + areg;
}
// B-perm index: (n row, kp pair) -> fragment-image slot
__device__ __forceinline__ size_t bpermidx(int n, int kp) {
    const int nb = n >> 7, r = n & 127;
    const int kb = kp >> 4, kr = kp & 15;
    const int kt = kr >> 3, khalf = (kr >> 2) & 1, j = kr & 3;
    return ((size_t)(nb * 32 + kb)) * 2048 +
           (kt * 16 + (r >> 3)) * 64 + ((r & 7) * 4 + j) * 2 + khalf;
}
// Q-frag slot for (bh, t, pair i)
__device__ __forceinline__ size_t qfragidx(int bh, int t, int i) {
    const int ks = i >> 3, kk2 = i & 7;
    const int c2 = kk2 & 3, khalf = kk2 >> 2;
    const int row = t & 127, qb = t >> 7;
    const int wq = row >> 4, wrow = row & 15;
    const int areg = ((wrow >> 3) & 1) | (khalf << 1);
    return (size_t)bh * 65536 + qb * 4096 +
           ((wq * 4 + ks) * 32 + (wrow & 7) * 4 + c2) * 4 + areg;
}
// K-frag slot for (bh, t, pair i)
__device__ __forceinline__ size_t kfragidx(int bh, int t, int i) {
    const int ks = i >> 3, kk2 = i & 7;
    const int c2 = kk2 & 3, khalf = kk2 >> 2;
    const int key = t & 63, ktile = t >> 6;
    return (size_t)bh * 65536 + ktile * 2048 +
           ((ks * 8 + (key >> 3)) * 32 + (key & 7) * 4 + c2) * 2 + khalf;
}

// ---------------------------------------------------------------------------
// splits
// ---------------------------------------------------------------------------
__global__ void split_permA(const float2* __restrict__ src,
                            uint32_t* __restrict__ dh, uint32_t* __restrict__ dl,
                            int total) {
    int i = blockIdx.x * blockDim.x + threadIdx.x;
    if (i >= total) return;
    float2 v = src[i];
    uint32_t lo, hi = split_pair(v.x, v.y, lo);
    const size_t idx = apermidx(i >> 9, i & 511);
    dh[idx] = hi; dl[idx] = lo;
}
__global__ void split_permB4(const float2* __restrict__ s0, const float2* __restrict__ s1,
                             const float2* __restrict__ s2, const float2* __restrict__ s3,
                             uint32_t* __restrict__ h0, uint32_t* __restrict__ l0,
                             uint32_t* __restrict__ h1, uint32_t* __restrict__ l1,
                             uint32_t* __restrict__ h2, uint32_t* __restrict__ l2,
                             uint32_t* __restrict__ h3, uint32_t* __restrict__ l3,
                             int total) {
    int i = blockIdx.x * blockDim.x + threadIdx.x;
    if (i >= total) return;
    const int which = blockIdx.y;
    const float2* src = which == 0 ? s0 : which == 1 ? s1 : which == 2 ? s2 : s3;
    uint32_t* dh = which == 0 ? h0 : which == 1 ? h1 : which == 2 ? h2 : h3;
    uint32_t* dl = which == 0 ? l0 : which == 1 ? l1 : which == 2 ? l2 : l3;
    float2 v = src[i];
    uint32_t lo, hi = split_pair(v.x, v.y, lo);
    const size_t idx = bpermidx(i >> 9, i & 511);
    dh[idx] = hi; dl[idx] = lo;
}

// ---------------------------------------------------------------------------
// Fused QKV GEMM (grid.x = 24: 8 n-blocks x {Q,K,V}). cp.async mainloop.
// Q is pre-scaled by 0.125*log2(e) so attention softmax runs in log2 domain.
// ---------------------------------------------------------------------------
#define QSCALE 0.18033688011112042f   // 0.125 * log2(e)

__global__ __launch_bounds__(256, 2)
void gemm_qkv(const uint32_t* __restrict__ Ah, const uint32_t* __restrict__ Al,
              const uint32_t* __restrict__ Wqh, const uint32_t* __restrict__ Wql,
              const uint32_t* __restrict__ Wkh, const uint32_t* __restrict__ Wkl,
              const uint32_t* __restrict__ Wvh, const uint32_t* __restrict__ Wvl,
              const float2* __restrict__ fc2,
              uint32_t* __restrict__ qfh, uint32_t* __restrict__ qfl,
              uint32_t* __restrict__ kfh, uint32_t* __restrict__ kfl,
              uint32_t* __restrict__ vfh, uint32_t* __restrict__ vfl) {
    extern __shared__ __align__(16) uint32_t sm[];   // 64KB

    const int which = blockIdx.x >> 3;               // 0=Q 1=K 2=V
    const int nblk  = blockIdx.x & 7;
    const uint32_t* Wh = which == 0 ? Wqh : which == 1 ? Wkh : Wvh;
    const uint32_t* Wl = which == 0 ? Wql : which == 1 ? Wkl : Wvl;

    const int tid  = threadIdx.x;
    const int lane = tid & 31;
    const int w    = tid >> 5;
    const int wm   = w & 1;
    const int wn   = w >> 1;
    const int m0   = blockIdx.y * 128;
    const int n0   = nblk * 128;
    const size_t abase = ((size_t)blockIdx.y * 32) * 2048;
    const size_t bbase = ((size_t)nblk * 32) * 2048;
    const uint32_t smaddr = smem_u32(sm);

    float acc[4][4][4];
    #pragma unroll
    for (int i = 0; i < 4; i++)
        #pragma unroll
        for (int j = 0; j < 4; j++)
            #pragma unroll
            for (int r = 0; r < 4; r++) acc[i][j][r] = 0.f;

    auto issue = [&](int st, int kb) {
        const uint32_t dbase = smaddr + (uint32_t)st * 32768u + tid * 32u;
        const size_t ko = (size_t)kb * 2048 + tid * 8;
        CP16(dbase,          Ah + abase + ko);
        CP16(dbase + 16,     Ah + abase + ko + 4);
        CP16(dbase + 8192,   Al + abase + ko);
        CP16(dbase + 8208,   Al + abase + ko + 4);
        CP16(dbase + 16384,  Wh + bbase + ko);
        CP16(dbase + 16400,  Wh + bbase + ko + 4);
        CP16(dbase + 24576,  Wl + bbase + ko);
        CP16(dbase + 24592,  Wl + bbase + ko + 4);
        asm volatile("cp.async.commit_group;" ::: "memory");
    };

    issue(0, 0);

    for (int kb = 0; kb < 32; kb++) {
        asm volatile("cp.async.wait_group 0;" ::: "memory");
        __syncthreads();
        if (kb < 31) issue((kb + 1) & 1, kb + 1);

        const uint32_t* As = sm + (kb & 1) * 8192;
        const uint32_t* Bs = As + 4096;

        #pragma unroll
        for (int kt2 = 0; kt2 < 2; kt2++) {
            uint4 Afh[4], Afl[4];
            uint2 Bfh[4], Bfl[4];
            const uint32_t* pa_ = &As[(kt2 * 8 + wm * 4) * 128 + lane * 4];
            #pragma unroll
            for (int i = 0; i < 4; i++) {
                Afh[i] = *(const uint4*)(pa_ + i * 128);
                Afl[i] = *(const uint4*)(pa_ + 2048 + i * 128);
            }
            const uint32_t* pb_ = &Bs[(kt2 * 16 + wn * 4) * 64 + lane * 2];
            #pragma unroll
            for (int i = 0; i < 4; i++) {
                Bfh[i] = *(const uint2*)(pb_ + i * 64);
                Bfl[i] = *(const uint2*)(pb_ + 2048 + i * 64);
            }
            #pragma unroll
            for (int mt = 0; mt < 4; mt++)
                #pragma unroll
                for (int nt = 0; nt < 4; nt++) {
                    mma16816(acc[mt][nt], (const uint32_t*)&Afh[mt], (const uint32_t*)&Bfh[nt]);
                    mma16816(acc[mt][nt], (const uint32_t*)&Afh[mt], (const uint32_t*)&Bfl[nt]);
                    mma16816(acc[mt][nt], (const uint32_t*)&Afl[mt], (const uint32_t*)&Bfh[nt]);
                }
        }
    }

    // epilogue
    #pragma unroll
    for (int mt = 0; mt < 4; mt++) {
        #pragma unroll
        for (int nt = 0; nt < 4; nt++) {
            const int m = m0 + wm * 64 + mt * 16 + (lane >> 2);
            const int n = n0 + wn * 32 + nt * 8 + ((lane & 3) << 1);  // even
            float* c = acc[mt][nt];
            const int b = m >> 11, t = m & 2047;
            const int h = n >> 6,  d = n & 63;
            const int bh = b * HH + h;
            if (which < 2) {
                const int i = d >> 1;
                #pragma unroll
                for (int rr = 0; rr < 2; rr++) {
                    const int tt = t + rr * 8;
                    const float2 cs = fc2[tt * 32 + i];
                    float o0 = c[rr*2] * cs.x - c[rr*2+1] * cs.y;
                    float o1 = c[rr*2] * cs.y + c[rr*2+1] * cs.x;
                    uint32_t lo, hi;
                    if (which == 0) {
                        hi = split_pair(o0 * QSCALE, o1 * QSCALE, lo);
                        const size_t qi = qfragidx(bh, tt, i);
                        qfh[qi] = hi; qfl[qi] = lo;
                    } else {
                        hi = split_pair(o0, o1, lo);
                        const size_t ki = kfragidx(bh, tt, i);
                        kfh[ki] = hi; kfl[ki] = lo;
                    }
                }
            } else {
                #pragma unroll
                for (int rr = 0; rr < 2; rr++) {
                    const int tt = t + rr * 8;
                    const int kt3 = tt >> 6, kpp = (tt & 63) >> 1, hf = tt & 1;
                    const int ks3 = kpp >> 3, kk3 = kpp & 7;
                    const int c3 = kk3 & 3, kh3 = kk3 >> 2;
                    #pragma unroll
                    for (int jj = 0; jj < 2; jj++) {
                        const int dd = d + jj;
                        const int slot = ((ks3 * 8 + (dd >> 3)) * 32 + (dd & 7) * 4 + c3) * 2 + kh3;
                        const size_t u32i = (size_t)bh * 65536 + kt3 * 2048 + slot;
                        const float v = c[rr * 2 + jj];
                        __nv_bfloat16 hb = __float2bfloat16_rn(v);
                        __nv_bfloat16 lb = __float2bfloat16_rn(v - __bfloat162float(hb));
                        ((uint16_t*)vfh)[u32i * 2 + hf] = *(uint16_t*)&hb;
                        ((uint16_t*)vfl)[u32i * 2 + hf] = *(uint16_t*)&lb;
                    }
                }
            }
        }
    }
}

// ---------------------------------------------------------------------------
// O-projection GEMM (A-perm x B-perm -> fp32 row-major out)
// ---------------------------------------------------------------------------
__global__ __launch_bounds__(256, 2)
void gemm_o(const uint32_t* __restrict__ Ah, const uint32_t* __restrict__ Al,
            const uint32_t* __restrict__ Wh, const uint32_t* __restrict__ Wl,
            float* __restrict__ C) {
    extern __shared__ __align__(16) uint32_t sm[];

    const int tid  = threadIdx.x;
    const int lane = tid & 31;
    const int w    = tid >> 5;
    const int wm   = w & 1;
    const int wn   = w >> 1;
    const int m0   = blockIdx.y * 128;
    const int n0   = blockIdx.x * 128;
    const size_t abase = ((size_t)blockIdx.y * 32) * 2048;
    const size_t bbase = ((size_t)blockIdx.x * 32) * 2048;
    const uint32_t smaddr = smem_u32(sm);

    float acc[4][4][4];
    #pragma unroll
    for (int i = 0; i < 4; i++)
        #pragma unroll
        for (int j = 0; j < 4; j++)
            #pragma unroll
            for (int r = 0; r < 4; r++) acc[i][j][r] = 0.f;

    auto issue = [&](int st, int kb) {
        const uint32_t dbase = smaddr + (uint32_t)st * 32768u + tid * 32u;
        const size_t ko = (size_t)kb * 2048 + tid * 8;
        CP16(dbase,          Ah + abase + ko);
        CP16(dbase + 16,     Ah + abase + ko + 4);
        CP16(dbase + 8192,   Al + abase + ko);
        CP16(dbase + 8208,   Al + abase + ko + 4);
        CP16(dbase + 16384,  Wh + bbase + ko);
        CP16(dbase + 16400,  Wh + bbase + ko + 4);
        CP16(dbase + 24576,  Wl + bbase + ko);
        CP16(dbase + 24592,  Wl + bbase + ko + 4);
        asm volatile("cp.async.commit_group;" ::: "memory");
    };

    issue(0, 0);

    for (int kb = 0; kb < 32; kb++) {
        asm volatile("cp.async.wait_group 0;" ::: "memory");
        __syncthreads();
        if (kb < 31) issue((kb + 1) & 1, kb + 1);

        const uint32_t* As = sm + (kb & 1) * 8192;
        const uint32_t* Bs = As + 4096;

        #pragma unroll
        for (int kt2 = 0; kt2 < 2; kt2++) {
            uint4 Afh[4], Afl[4];
            uint2 Bfh[4], Bfl[4];
            const uint32_t* pa_ = &As[(kt2 * 8 + wm * 4) * 128 + lane * 4];
            #pragma unroll
            for (int i = 0; i < 4; i++) {
                Afh[i] = *(const uint4*)(pa_ + i * 128);
                Afl[i] = *(const uint4*)(pa_ + 2048 + i * 128);
            }
            const uint32_t* pb_ = &Bs[(kt2 * 16 + wn * 4) * 64 + lane * 2];
            #pragma unroll
            for (int i = 0; i < 4; i++) {
                Bfh[i] = *(const uint2*)(pb_ + i * 64);
                Bfl[i] = *(const uint2*)(pb_ + 2048 + i * 64);
            }
            #pragma unroll
            for (int mt = 0; mt < 4; mt++)
                #pragma unroll
                for (int nt = 0; nt < 4; nt++) {
                    mma16816(acc[mt][nt], (const uint32_t*)&Afh[mt], (const uint32_t*)&Bfh[nt]);
                    mma16816(acc[mt][nt], (const uint32_t*)&Afh[mt], (const uint32_t*)&Bfl[nt]);
                    mma16816(acc[mt][nt], (const uint32_t*)&Afl[mt], (const uint32_t*)&Bfh[nt]);
                }
        }
    }

    #pragma unroll
    for (int mt = 0; mt < 4; mt++) {
        #pragma unroll
        for (int nt = 0; nt < 4; nt++) {
            const int m = m0 + wm * 64 + mt * 16 + (lane >> 2);
            const int n = n0 + wn * 32 + nt * 8 + ((lane & 3) << 1);
            const float* c = acc[mt][nt];
            *(float2*)&C[(size_t)m * 1024 + n]       = make_float2(c[0], c[1]);
            *(float2*)&C[(size_t)(m + 8) * 1024 + n] = make_float2(c[2], c[3]);
        }
    }
}

// ---------------------------------------------------------------------------
// Tensor-core flash attention (mma.sync, causal, log2-domain softmax).
// 1D grid heavy-first: idx -> qi = 15 - idx/32, bh = idx%32. 2 CTAs/SM.
// smem: [2 stages x 8192 u32][Q-lo 4096 u32] = 80KB.
// ---------------------------------------------------------------------------
__global__ __launch_bounds__(256, 2)
void attn_mma(const uint32_t* __restrict__ qfh, const uint32_t* __restrict__ qfl,
              const uint32_t* __restrict__ kfh, const uint32_t* __restrict__ kfl,
              const uint32_t* __restrict__ vfh, const uint32_t* __restrict__ vfl,
              uint32_t* __restrict__ aoh, uint32_t* __restrict__ aol) {
    extern __shared__ __align__(16) uint32_t sm[];
    const int qi = 15 - (blockIdx.x >> 5);
    const int bh = blockIdx.x & 31;
    const int b  = bh >> 4, hhd = bh & 15;
    const int q0 = qi * 128;
    const int tid = threadIdx.x;
    const int lane = tid & 31;
    const int w = tid >> 5;
    const uint32_t smaddr = smem_u32(sm);
    const size_t hbase = (size_t)bh * 65536;
    uint32_t* qlo_s = sm + 16384;

    uint4 qfh_r[4];
    {
        const size_t qb = hbase + (size_t)qi * 4096;
        #pragma unroll
        for (int ks = 0; ks < 4; ks++) {
            const size_t o = qb + ((w * 4 + ks) * 32 + lane) * 4;
            qfh_r[ks] = *(const uint4*)&qfh[o];
        }
        #pragma unroll
        for (int i = 0; i < 4; i++) {
            const int id = i * 1024 + tid * 4;
            *(uint4*)&qlo_s[id] = *(const uint4*)&qfl[qb + id];
        }
    }
    __syncthreads();

    float oacc[8][4];
    #pragma unroll
    for (int dt = 0; dt < 8; dt++)
        #pragma unroll
        for (int r = 0; r < 4; r++) oacc[dt][r] = 0.f;
    float mr0 = -1e30f, mr1 = -1e30f, lr0 = 0.f, lr1 = 0.f;

    const int r0 = q0 + w * 16;
    const int ntiles = qi * 2 + 2;

    auto issue = [&](int st, int kt) {
        const uint32_t dbase = smaddr + (uint32_t)st * 32768u + tid * 32u;
        const size_t ko = hbase + (size_t)kt * 2048 + tid * 8;
        CP16(dbase,          kfh + ko);
        CP16(dbase + 16,     kfh + ko + 4);
        CP16(dbase + 8192,   kfl + ko);
        CP16(dbase + 8208,   kfl + ko + 4);
        CP16(dbase + 16384,  vfh + ko);
        CP16(dbase + 16400,  vfh + ko + 4);
        CP16(dbase + 24576,  vfl + ko);
        CP16(dbase + 24592,  vfl + ko + 4);
        asm volatile("cp.async.commit_group;" ::: "memory");
    };

    issue(0, 0);

    for (int kt = 0; kt < ntiles; kt++) {
        const int kt0 = kt * 64;
        asm volatile("cp.async.wait_group 0;" ::: "memory");
        __syncthreads();
        if (kt + 1 < ntiles) issue((kt + 1) & 1, kt + 1);

        const uint32_t* S = sm + (kt & 1) * 8192;

        if (kt0 <= r0 + 15) {
            float sacc[8][4];
            #pragma unroll
            for (int nt = 0; nt < 8; nt++) {
                #pragma unroll
                for (int r = 0; r < 4; r++) sacc[nt][r] = 0.f;
                #pragma unroll
                for (int ks = 0; ks < 4; ks++) {
                    uint4 qlo = *(const uint4*)&qlo_s[((w * 4 + ks) * 32 + lane) * 4];
                    uint2 kbh = *(const uint2*)&S[((ks * 8 + nt) * 32 + lane) * 2];
                    uint2 kbl = *(const uint2*)&S[2048 + ((ks * 8 + nt) * 32 + lane) * 2];
                    mma16816(sacc[nt], (const uint32_t*)&qfh_r[ks], (const uint32_t*)&kbh);
                    mma16816(sacc[nt], (const uint32_t*)&qfh_r[ks], (const uint32_t*)&kbl);
                    mma16816(sacc[nt], (const uint32_t*)&qlo, (const uint32_t*)&kbh);
                }
            }
            if (kt0 + 63 > r0) {
                const int colb = kt0 + ((lane & 3) << 1);
                const int rowb = r0 + (lane >> 2);
                #pragma unroll
                for (int nt = 0; nt < 8; nt++) {
                    #pragma unroll
                    for (int r = 0; r < 4; r++) {
                        const int col = colb + nt * 8 + (r & 1);
                        const int row = rowb + ((r >> 1) << 3);
                        if (col > row) sacc[nt][r] = -1e30f;
                    }
                }
            }
            float mx0 = -1e30f, mx1 = -1e30f;
            #pragma unroll
            for (int nt = 0; nt < 8; nt++) {
                mx0 = fmaxf(mx0, fmaxf(sacc[nt][0], sacc[nt][1]));
                mx1 = fmaxf(mx1, fmaxf(sacc[nt][2], sacc[nt][3]));
            }
            mx0 = fmaxf(mx0, __shfl_xor_sync(0xffffffffu, mx0, 1));
            mx0 = fmaxf(mx0, __shfl_xor_sync(0xffffffffu, mx0, 2));
            mx1 = fmaxf(mx1, __shfl_xor_sync(0xffffffffu, mx1, 1));
            mx1 = fmaxf(mx1, __shfl_xor_sync(0xffffffffu, mx1, 2));
            const float mn0 = fmaxf(mr0, mx0);
            const float mn1 = fmaxf(mr1, mx1);
            const float corr0 = ex2f(mr0 - mn0);   // log2-domain
            const float corr1 = ex2f(mr1 - mn1);
            mr0 = mn0; mr1 = mn1;
            float s0 = 0.f, s1 = 0.f;
            #pragma unroll
            for (int nt = 0; nt < 8; nt++) {
                sacc[nt][0] = ex2f(sacc[nt][0] - mn0);
                sacc[nt][1] = ex2f(sacc[nt][1] - mn0);
                sacc[nt][2] = ex2f(sacc[nt][2] - mn1);
                sacc[nt][3] = ex2f(sacc[nt][3] - mn1);
                s0 += sacc[nt][0] + sacc[nt][1];
                s1 += sacc[nt][2] + sacc[nt][3];
            }
            lr0 = lr0 * corr0 + s0;
            lr1 = lr1 * corr1 + s1;
            #pragma unroll
            for (int dt = 0; dt < 8; dt++) {
                oacc[dt][0] *= corr0; oacc[dt][1] *= corr0;
                oacc[dt][2] *= corr1; oacc[dt][3] *= corr1;
            }
            uint32_t pah[4][4], pal[4][4];
            #pragma unroll
            for (int ksp = 0; ksp < 4; ksp++) {
                pah[ksp][0] = split_pair(sacc[2*ksp][0],   sacc[2*ksp][1],   pal[ksp][0]);
                pah[ksp][1] = split_pair(sacc[2*ksp][2],   sacc[2*ksp][3],   pal[ksp][1]);
                pah[ksp][2] = split_pair(sacc[2*ksp+1][0], sacc[2*ksp+1][1], pal[ksp][2]);
                pah[ksp][3] = split_pair(sacc[2*ksp+1][2], sacc[2*ksp+1][3], pal[ksp][3]);
            }
            #pragma unroll
            for (int dt = 0; dt < 8; dt++) {
                #pragma unroll
                for (int ksp = 0; ksp < 4; ksp++) {
                    uint2 vbh = *(const uint2*)&S[4096 + ((ksp * 8 + dt) * 32 + lane) * 2];
                    uint2 vbl = *(const uint2*)&S[6144 + ((ksp * 8 + dt) * 32 + lane) * 2];
                    mma16816(oacc[dt], pah[ksp], (const uint32_t*)&vbh);
                    mma16816(oacc[dt], pal[ksp], (const uint32_t*)&vbh);
                    mma16816(oacc[dt], pah[ksp], (const uint32_t*)&vbl);
                }
            }
        }
    }

    lr0 += __shfl_xor_sync(0xffffffffu, lr0, 1);
    lr0 += __shfl_xor_sync(0xffffffffu, lr0, 2);
    lr1 += __shfl_xor_sync(0xffffffffu, lr1, 1);
    lr1 += __shfl_xor_sync(0xffffffffu, lr1, 2);
    const float inv0 = 1.f / lr0;
    const float inv1 = 1.f / lr1;
    const int t0 = r0 + (lane >> 2);
    const int t1 = t0 + 8;
    #pragma unroll
    for (int dt = 0; dt < 8; dt++) {
        const int kp = hhd * 32 + dt * 4 + (lane & 3);
        uint32_t lo;
        uint32_t hi = split_pair(oacc[dt][0] * inv0, oacc[dt][1] * inv0, lo);
        const size_t i0 = apermidx(b * TT + t0, kp);
        aoh[i0] = hi; aol[i0] = lo;
        hi = split_pair(oacc[dt][2] * inv1, oacc[dt][3] * inv1, lo);
        const size_t i1 = apermidx(b * TT + t1, kp);
        aoh[i1] = hi; aol[i1] = lo;
    }
}

// ---------------------------------------------------------------------------
extern "C" void kernel_launch(void* const* d_in, const int* in_sizes, int n_in,
                              void* d_out, int out_size) {
    const float* x  = (const float*)d_in[0];
    const float* wq = (const float*)d_in[1];
    const float* wk = (const float*)d_in[2];
    const float* wv = (const float*)d_in[3];
    const float* wo = (const float*)d_in[4];
    const float* fc = (const float*)d_in[5];
    float* out = (float*)d_out;

    uint32_t *qfhp, *qflp, *kfhp, *kflp, *vfhp, *vflp;
    uint32_t *xhp, *xlp, *aohp, *aolp;
    uint32_t *wqhp, *wqlp, *wkhp, *wklp, *wvhp, *wvlp, *wohp, *wolp;
    cudaGetSymbolAddress((void**)&qfhp, g_qfh);
    cudaGetSymbolAddress((void**)&qflp, g_qfl);
    cudaGetSymbolAddress((void**)&kfhp, g_kfh);
    cudaGetSymbolAddress((void**)&kflp, g_kfl);
    cudaGetSymbolAddress((void**)&vfhp, g_vfh);
    cudaGetSymbolAddress((void**)&vflp, g_vfl);
    cudaGetSymbolAddress((void**)&xhp, g_xh);
    cudaGetSymbolAddress((void**)&xlp, g_xl);
    cudaGetSymbolAddress((void**)&aohp, g_aoh);
    cudaGetSymbolAddress((void**)&aolp, g_aol);
    cudaGetSymbolAddress((void**)&wqhp, g_wqh);
    cudaGetSymbolAddress((void**)&wqlp, g_wql);
    cudaGetSymbolAddress((void**)&wkhp, g_wkh);
    cudaGetSymbolAddress((void**)&wklp, g_wkl);
    cudaGetSymbolAddress((void**)&wvhp, g_wvh);
    cudaGetSymbolAddress((void**)&wvlp, g_wvl);
    cudaGetSymbolAddress((void**)&wohp, g_woh);
    cudaGetSymbolAddress((void**)&wolp, g_wol);

    const int DYNSZ  = 65536;
    const int ADYNSZ = 81920;
    cudaFuncSetAttribute(gemm_qkv, cudaFuncAttributeMaxDynamicSharedMemorySize, DYNSZ);
    cudaFuncSetAttribute(gemm_o,   cudaFuncAttributeMaxDynamicSharedMemorySize, DYNSZ);
    cudaFuncSetAttribute(attn_mma, cudaFuncAttributeMaxDynamicSharedMemorySize, ADYNSZ);

    const int xpairs = M_ROWS * 512;
    const int wpairs = DD * 512;
    split_permA<<<(xpairs + 255) / 256, 256>>>((const float2*)x, xhp, xlp, xpairs);
    dim3 sgrid((wpairs + 255) / 256, 4);
    split_permB4<<<sgrid, 256>>>((const float2*)wq, (const float2*)wk,
                                 (const float2*)wv, (const float2*)wo,
                                 wqhp, wqlp, wkhp, wklp, wvhp, wvlp, wohp, wolp,
                                 wpairs);

    dim3 qkvgrid(24, M_ROWS / 128);   // (24, 32)
    gemm_qkv<<<qkvgrid, 256, DYNSZ>>>(xhp, xlp, wqhp, wqlp, wkhp, wklp, wvhp, wvlp,
                                      (const float2*)fc, qfhp, qflp, kfhp, kflp,
                                      vfhp, vflp);

    attn_mma<<<512, 256, ADYNSZ>>>(qfhp, qflp, kfhp, kflp, vfhp, vflp, aohp, aolp);

    dim3 ogrid(DD / 128, M_ROWS / 128);
    gemm_o<<<ogrid, 256, DYNSZ>>>(aohp, aolp, wohp, wolp, out);
}